// round 6
// baseline (speedup 1.0000x reference)
#include <cuda_runtime.h>
#include <cstdint>

#define NNODES 100000
#define EDGES  1600000
#define IN_F   165
#define HID    128

// Scratch (allocation-free rule: __device__ globals)
__device__ float g_bufG[(size_t)NNODES * HID];   // (x@W)*dinv
__device__ float g_bufH[(size_t)NNODES * HID];   // layer-1 activation
__device__ int   g_deg[NNODES];
__device__ float g_dinv[NNODES];
__device__ int   g_rowptr[NNODES + 1];
__device__ int   g_cnt[NNODES];
__device__ int   g_csr_src[EDGES];
__device__ int   g_blockSums[128];

// ---------------- degree ----------------

__global__ void zero2_int_kernel(int* __restrict__ a, int* __restrict__ b, int n) {
    int i = blockIdx.x * blockDim.x + threadIdx.x;
    if (i < n) { a[i] = 0; b[i] = 0; }
}

__global__ void deg_kernel(const int* __restrict__ dst, int* __restrict__ deg, int e) {
    int i = blockIdx.x * blockDim.x + threadIdx.x;
    if (i < e) atomicAdd(&deg[dst[i]], 1);
}

// ---------------- exclusive prefix scan of deg -> rowptr; also dinv ----------------

__global__ __launch_bounds__(256)
void scan_block_sums(const int* __restrict__ deg, int* __restrict__ blockSums, int n) {
    __shared__ int sdata[256];
    int base = blockIdx.x * 2048;
    int tid = threadIdx.x;
    int s = 0;
#pragma unroll
    for (int j = 0; j < 8; j++) {
        int i = base + tid * 8 + j;
        if (i < n) s += deg[i];
    }
    sdata[tid] = s;
    __syncthreads();
    for (int off = 128; off; off >>= 1) {
        if (tid < off) sdata[tid] += sdata[tid + off];
        __syncthreads();
    }
    if (tid == 0) blockSums[blockIdx.x] = sdata[0];
}

// parallel exclusive scan of up to 64 block sums (one warp, 2 elems/lane)
__global__ void scan_offsets(int* __restrict__ blockSums, int nb) {
    int lane = threadIdx.x;            // 32 threads
    int v0 = (lane      < nb) ? blockSums[lane]      : 0;
    int v1 = (lane + 32 < nb) ? blockSums[lane + 32] : 0;
    // inclusive warp scan of v0
    int s0 = v0;
#pragma unroll
    for (int off = 1; off < 32; off <<= 1) {
        int t = __shfl_up_sync(0xFFFFFFFFu, s0, off);
        if (lane >= off) s0 += t;
    }
    int total0 = __shfl_sync(0xFFFFFFFFu, s0, 31);
    int s1 = v1;
#pragma unroll
    for (int off = 1; off < 32; off <<= 1) {
        int t = __shfl_up_sync(0xFFFFFFFFu, s1, off);
        if (lane >= off) s1 += t;
    }
    if (lane      < nb) blockSums[lane]      = s0 - v0;            // exclusive
    if (lane + 32 < nb) blockSums[lane + 32] = total0 + s1 - v1;
}

__global__ __launch_bounds__(256)
void scan_final(const int* __restrict__ deg, const int* __restrict__ blockSums,
                int* __restrict__ rowptr, float* __restrict__ dinv, int n) {
    __shared__ int tsum[256];
    int base = blockIdx.x * 2048;
    int tid = threadIdx.x;
    int loc[8];
    int dv[8];
    int s = 0;
#pragma unroll
    for (int j = 0; j < 8; j++) {
        int i = base + tid * 8 + j;
        int v = (i < n) ? deg[i] : 0;
        dv[j]  = v;
        loc[j] = s;
        s += v;
    }
    tsum[tid] = s;
    __syncthreads();
    for (int off = 1; off < 256; off <<= 1) {
        int t = (tid >= off) ? tsum[tid - off] : 0;
        __syncthreads();
        tsum[tid] += t;
        __syncthreads();
    }
    int threadOff = tsum[tid] - s;  // exclusive within block
    int cOff = blockSums[blockIdx.x];
#pragma unroll
    for (int j = 0; j < 8; j++) {
        int i = base + tid * 8 + j;
        if (i < n) {
            int rp = cOff + threadOff + loc[j];
            rowptr[i] = rp;
            dinv[i]   = rsqrtf((float)(dv[j] + 1));   // +1 self-loop
            if (i == n - 1) rowptr[n] = rp + dv[j];
        }
    }
}

// ---------------- scatter edges into CSR slots ----------------

__global__ void scatter_kernel(const int* __restrict__ src, const int* __restrict__ dst,
                               const int* __restrict__ rowptr, int* __restrict__ cnt,
                               int* __restrict__ csr, int e) {
    int i = blockIdx.x * blockDim.x + threadIdx.x;
    if (i < e) {
        int d = dst[i];
        int pos = rowptr[d] + atomicAdd(&cnt[d], 1);
        csr[pos] = src[i];
    }
}

// ---------------- tf32 helpers ----------------

__device__ __forceinline__ void split_tf32(float v, float& hi, float& lo) {
    uint32_t h;
    asm("cvt.rna.tf32.f32 %0, %1;" : "=r"(h) : "f"(v));
    float hf = __uint_as_float(h);
    float r = v - hf;                     // exact residual
    uint32_t l;
    asm("cvt.rna.tf32.f32 %0, %1;" : "=r"(l) : "f"(r));
    hi = hf;
    lo = __uint_as_float(l);
}

__device__ __forceinline__ void mma_tf32(float* d,
                                         uint32_t a0, uint32_t a1, uint32_t a2, uint32_t a3,
                                         uint32_t b0, uint32_t b1) {
    asm volatile(
        "mma.sync.aligned.m16n8k8.row.col.f32.tf32.tf32.f32 "
        "{%0,%1,%2,%3}, {%4,%5,%6,%7}, {%8,%9}, {%0,%1,%2,%3};"
        : "+f"(d[0]), "+f"(d[1]), "+f"(d[2]), "+f"(d[3])
        : "r"(a0), "r"(a1), "r"(a2), "r"(a3), "r"(b0), "r"(b1));
}

// ---------------- GEMM (tensor, 3xtf32, double-buffered): --------------------------
// G[n,128] = (A[n,K] @ W[K,128]) * dinv[row]
// 128x128 tile, BK=16, 256 threads = 8 warps (2x4), each warp 64x32 (4x4 m16n8k8).
// A,W split into tf32 hi/lo in smem; D = Ah*Wh + Al*Wh + Ah*Wl (error ~2^-22).
// Smem ping-pong: one __syncthreads per tile; loads for t+1 overlap MMAs of t.

#define GEMM_BK  16
#define GEMM_LD  136
#define GEMM_TILE_F (GEMM_BK * GEMM_LD)          // 2176 floats per array
#define GEMM_SMEM_BYTES (2 * 4 * GEMM_TILE_F * 4) // 69632 B

template <int K>
__global__ __launch_bounds__(256)
void gemm_tf32_kernel(const float* __restrict__ A, const float* __restrict__ W,
                      const float* __restrict__ dinv, float* __restrict__ G, int n) {
    constexpr int BM = 128, BN = 128, BK = GEMM_BK;
    constexpr int LD = GEMM_LD;
    constexpr int TILES = (K + BK - 1) / BK;

    extern __shared__ float smem[];
    // per buffer: [Ah | Al | Bh | Bl], each GEMM_TILE_F floats
    auto AH = [&](int buf) { return smem + buf * 4 * GEMM_TILE_F + 0 * GEMM_TILE_F; };
    auto AL = [&](int buf) { return smem + buf * 4 * GEMM_TILE_F + 1 * GEMM_TILE_F; };
    auto BH = [&](int buf) { return smem + buf * 4 * GEMM_TILE_F + 2 * GEMM_TILE_F; };
    auto BL = [&](int buf) { return smem + buf * 4 * GEMM_TILE_F + 3 * GEMM_TILE_F; };

    const int tid  = threadIdx.x;
    const int wid  = tid >> 5;
    const int lane = tid & 31;
    const int g    = lane >> 2;   // group id 0..7
    const int tig  = lane & 3;    // thread in group 0..3
    const int wm   = wid & 1;     // 0..1 (64 rows each)
    const int wn   = wid >> 1;    // 0..3 (32 cols each)
    const int rowBase = blockIdx.x * BM;

    float acc[4][4][4];
#pragma unroll
    for (int mf = 0; mf < 4; mf++)
#pragma unroll
        for (int nf = 0; nf < 4; nf++)
#pragma unroll
            for (int q = 0; q < 4; q++) acc[mf][nf][q] = 0.f;

    auto loadAB = [&](int t, int buf) {
        const int k0 = t * BK;
        float* ah = AH(buf); float* al = AL(buf);
        float* bh = BH(buf); float* bl = BL(buf);
        // A tile [BM][BK] -> ah/al[kk*LD + m] (transposed)
#pragma unroll
        for (int j = 0; j < 8; j++) {
            int l  = tid + 256 * j;
            int m  = l >> 4;
            int kk = l & 15;
            int gr = rowBase + m;
            int gk = k0 + kk;
            float v = 0.f;
            if (gr < n && gk < K) v = A[(size_t)gr * K + gk];
            float hi, lo;
            split_tf32(v, hi, lo);
            ah[kk * LD + m] = hi;
            al[kk * LD + m] = lo;
        }
        // W tile [BK][BN] -> bh/bl[kk*LD + n] (vectorized)
#pragma unroll
        for (int j = 0; j < 2; j++) {
            int l4 = tid * 2 + j;          // 512 float4
            int kk = l4 >> 5;
            int n4 = l4 & 31;
            int gk = k0 + kk;
            float4 v = make_float4(0.f, 0.f, 0.f, 0.f);
            if (gk < K) v = *(const float4*)&W[(size_t)gk * BN + n4 * 4];
            float4 hi, lo;
            split_tf32(v.x, hi.x, lo.x);
            split_tf32(v.y, hi.y, lo.y);
            split_tf32(v.z, hi.z, lo.z);
            split_tf32(v.w, hi.w, lo.w);
            *(float4*)&bh[kk * LD + n4 * 4] = hi;
            *(float4*)&bl[kk * LD + n4 * 4] = lo;
        }
    };

    loadAB(0, 0);
    __syncthreads();

    for (int t = 0; t < TILES; t++) {
        const int cur = t & 1;
        // issue next tile's loads while computing current (different buffer)
        if (t + 1 < TILES) loadAB(t + 1, cur ^ 1);

        const float* ah = AH(cur); const float* al = AL(cur);
        const float* bhs = BH(cur); const float* bls = BL(cur);

#pragma unroll
        for (int kh = 0; kh < 2; kh++) {
            const int k8 = kh * 8;
            uint32_t bh[4][2], bl[4][2];
#pragma unroll
            for (int nf = 0; nf < 4; nf++) {
                int c = wn * 32 + nf * 8 + g;
                bh[nf][0] = __float_as_uint(bhs[(k8 + tig) * LD + c]);
                bh[nf][1] = __float_as_uint(bhs[(k8 + tig + 4) * LD + c]);
                bl[nf][0] = __float_as_uint(bls[(k8 + tig) * LD + c]);
                bl[nf][1] = __float_as_uint(bls[(k8 + tig + 4) * LD + c]);
            }
#pragma unroll
            for (int mf = 0; mf < 4; mf++) {
                int r = wm * 64 + mf * 16 + g;
                uint32_t ah0 = __float_as_uint(ah[(k8 + tig) * LD + r]);
                uint32_t ah1 = __float_as_uint(ah[(k8 + tig) * LD + r + 8]);
                uint32_t ah2 = __float_as_uint(ah[(k8 + tig + 4) * LD + r]);
                uint32_t ah3 = __float_as_uint(ah[(k8 + tig + 4) * LD + r + 8]);
                uint32_t al0 = __float_as_uint(al[(k8 + tig) * LD + r]);
                uint32_t al1 = __float_as_uint(al[(k8 + tig) * LD + r + 8]);
                uint32_t al2 = __float_as_uint(al[(k8 + tig + 4) * LD + r]);
                uint32_t al3 = __float_as_uint(al[(k8 + tig + 4) * LD + r + 8]);
#pragma unroll
                for (int nf = 0; nf < 4; nf++) {
                    mma_tf32(acc[mf][nf], ah0, ah1, ah2, ah3, bh[nf][0], bh[nf][1]);
                    mma_tf32(acc[mf][nf], al0, al1, al2, al3, bh[nf][0], bh[nf][1]);
                    mma_tf32(acc[mf][nf], ah0, ah1, ah2, ah3, bl[nf][0], bl[nf][1]);
                }
            }
        }
        __syncthreads();
    }

    // ---- epilogue: scale by dinv, store ----
#pragma unroll
    for (int mf = 0; mf < 4; mf++) {
        int r0 = rowBase + wm * 64 + mf * 16 + g;
        int r1 = r0 + 8;
        float s0 = (r0 < n) ? dinv[r0] : 0.f;
        float s1 = (r1 < n) ? dinv[r1] : 0.f;
#pragma unroll
        for (int nf = 0; nf < 4; nf++) {
            int c = wn * 32 + nf * 8 + tig * 2;
            if (r0 < n) {
                float2 o = make_float2(acc[mf][nf][0] * s0, acc[mf][nf][1] * s0);
                *(float2*)&G[(size_t)r0 * 128 + c] = o;
            }
            if (r1 < n) {
                float2 o = make_float2(acc[mf][nf][2] * s1, acc[mf][nf][3] * s1);
                *(float2*)&G[(size_t)r1 * 128 + c] = o;
            }
        }
    }
}

// ---------------- fused aggregation: warp per node, CSR segment, no atomics --------

template <bool FINAL>
__global__ __launch_bounds__(256)
void agg_fused_kernel(const float4* __restrict__ g, const int* __restrict__ csr,
                      const int* __restrict__ rowptr,
                      const float* __restrict__ dinv, const float4* __restrict__ bias,
                      float4* __restrict__ h,
                      const float4* __restrict__ Wc4, const float* __restrict__ bc,
                      float2* __restrict__ out, int n) {
    int node = (blockIdx.x * blockDim.x + threadIdx.x) >> 5;
    int lane = threadIdx.x & 31;
    if (node >= n) return;

    const int start = rowptr[node];
    const int end   = rowptr[node + 1];
    const int cnt   = end - start;

    float4 a[8];
    a[0] = g[(size_t)node * 32 + lane];  // self-loop term
#pragma unroll
    for (int i = 1; i < 8; i++) a[i] = make_float4(0.f, 0.f, 0.f, 0.f);

    int j = 0;
    for (; j + 8 <= cnt; j += 8) {
        int idx[8];
#pragma unroll
        for (int u = 0; u < 8; u++) idx[u] = __ldg(&csr[start + j + u]);
#pragma unroll
        for (int u = 0; u < 8; u++) {
            float4 v = g[(size_t)idx[u] * 32 + lane];
            a[u].x += v.x; a[u].y += v.y; a[u].z += v.z; a[u].w += v.w;
        }
    }
    if (j + 4 <= cnt) {
        int idx[4];
#pragma unroll
        for (int u = 0; u < 4; u++) idx[u] = __ldg(&csr[start + j + u]);
#pragma unroll
        for (int u = 0; u < 4; u++) {
            float4 v = g[(size_t)idx[u] * 32 + lane];
            a[u].x += v.x; a[u].y += v.y; a[u].z += v.z; a[u].w += v.w;
        }
        j += 4;
    }
    for (; j < cnt; j++) {
        int s0 = __ldg(&csr[start + j]);
        float4 v = g[(size_t)s0 * 32 + lane];
        a[0].x += v.x; a[0].y += v.y; a[0].z += v.z; a[0].w += v.w;
    }

    float4 acc;
    acc.x = ((a[0].x + a[1].x) + (a[2].x + a[3].x)) + ((a[4].x + a[5].x) + (a[6].x + a[7].x));
    acc.y = ((a[0].y + a[1].y) + (a[2].y + a[3].y)) + ((a[4].y + a[5].y) + (a[6].y + a[7].y));
    acc.z = ((a[0].z + a[1].z) + (a[2].z + a[3].z)) + ((a[4].z + a[5].z) + (a[6].z + a[7].z));
    acc.w = ((a[0].w + a[1].w) + (a[2].w + a[3].w)) + ((a[4].w + a[5].w) + (a[6].w + a[7].w));

    float s = dinv[node];
    float4 bv = bias[lane];
    float4 hv;
    hv.x = fmaxf(fmaf(s, acc.x, bv.x), 0.f);
    hv.y = fmaxf(fmaf(s, acc.y, bv.y), 0.f);
    hv.z = fmaxf(fmaf(s, acc.z, bv.z), 0.f);
    hv.w = fmaxf(fmaf(s, acc.w, bv.w), 0.f);

    if (!FINAL) {
        h[(size_t)node * 32 + lane] = hv;
    } else {
        float4 w0 = __ldg(&Wc4[lane * 2]);
        float4 w1 = __ldg(&Wc4[lane * 2 + 1]);
        float p0 = hv.x * w0.x + hv.y * w0.z + hv.z * w1.x + hv.w * w1.z;
        float p1 = hv.x * w0.y + hv.y * w0.w + hv.z * w1.y + hv.w * w1.w;
#pragma unroll
        for (int off = 16; off; off >>= 1) {
            p0 += __shfl_xor_sync(0xFFFFFFFFu, p0, off);
            p1 += __shfl_xor_sync(0xFFFFFFFFu, p1, off);
        }
        if (lane == 0) out[node] = make_float2(p0 + bc[0], p1 + bc[1]);
    }
}

// ---------------- launch ----------------

extern "C" void kernel_launch(void* const* d_in, const int* in_sizes, int n_in,
                              void* d_out, int out_size) {
    const float* x  = (const float*)d_in[0];
    const int*   ei = (const int*)d_in[1];
    const float* W1 = (const float*)d_in[2];
    const float* b1 = (const float*)d_in[3];
    const float* W2 = (const float*)d_in[4];
    const float* b2 = (const float*)d_in[5];
    const float* Wc = (const float*)d_in[6];
    const float* bc = (const float*)d_in[7];
    float* out = (float*)d_out;

    const int n = NNODES;
    const int e = in_sizes[1] / 2;
    const int* src = ei;
    const int* dst = ei + e;

    float *G, *H, *DINV;
    int *DEG, *ROWPTR, *CNT, *CSR, *BSUMS;
    cudaGetSymbolAddress((void**)&G,      g_bufG);
    cudaGetSymbolAddress((void**)&H,      g_bufH);
    cudaGetSymbolAddress((void**)&DINV,   g_dinv);
    cudaGetSymbolAddress((void**)&DEG,    g_deg);
    cudaGetSymbolAddress((void**)&ROWPTR, g_rowptr);
    cudaGetSymbolAddress((void**)&CNT,    g_cnt);
    cudaGetSymbolAddress((void**)&CSR,    g_csr_src);
    cudaGetSymbolAddress((void**)&BSUMS,  g_blockSums);

    // raise dynamic smem limits (host-side attribute set; not a captured op)
    static bool attrDone = false;
    if (!attrDone) {
        cudaFuncSetAttribute(gemm_tf32_kernel<IN_F>,
                             cudaFuncAttributeMaxDynamicSharedMemorySize, GEMM_SMEM_BYTES);
        cudaFuncSetAttribute(gemm_tf32_kernel<HID>,
                             cudaFuncAttributeMaxDynamicSharedMemorySize, GEMM_SMEM_BYTES);
        attrDone = true;
    }

    const int gemmB = (n + 127) / 128;
    const int aggB  = (int)(((long long)n * 32 + 255) / 256);
    const int scanB = (n + 2047) / 2048;

    // ---- graph preprocessing ----
    zero2_int_kernel<<<(n + 255) / 256, 256>>>(DEG, CNT, n);
    deg_kernel<<<(e + 255) / 256, 256>>>(dst, DEG, e);
    scan_block_sums<<<scanB, 256>>>(DEG, BSUMS, n);
    scan_offsets<<<1, 32>>>(BSUMS, scanB);
    scan_final<<<scanB, 256>>>(DEG, BSUMS, ROWPTR, DINV, n);
    scatter_kernel<<<(e + 255) / 256, 256>>>(src, dst, ROWPTR, CNT, CSR, e);

    // ---- layer 1 ----
    gemm_tf32_kernel<IN_F><<<gemmB, 256, GEMM_SMEM_BYTES>>>(x, W1, DINV, G, n);
    agg_fused_kernel<false><<<aggB, 256>>>((const float4*)G, CSR, ROWPTR, DINV,
                                           (const float4*)b1, (float4*)H,
                                           nullptr, nullptr, nullptr, n);

    // ---- layer 2 (+ fused classifier) ----
    gemm_tf32_kernel<HID><<<gemmB, 256, GEMM_SMEM_BYTES>>>(H, W2, DINV, G, n);
    agg_fused_kernel<true><<<aggB, 256>>>((const float4*)G, CSR, ROWPTR, DINV,
                                          (const float4*)b2, nullptr,
                                          (const float4*)Wc, bc, (float2*)out, n);
}

// round 7
// speedup vs baseline: 1.0648x; 1.0648x over previous
#include <cuda_runtime.h>
#include <cstdint>

#define NNODES 100000
#define EDGES  1600000
#define IN_F   165
#define HID    128

// Scratch (allocation-free rule: __device__ globals)
__device__ float g_bufG[(size_t)NNODES * HID];   // x@W (unscaled)
__device__ float g_bufH[(size_t)NNODES * HID];   // layer-1 activation, pre-scaled by dinv
__device__ int   g_deg[NNODES];                  // self-restoring: scatter counts it back to 0
__device__ float g_dinv[NNODES];
__device__ int   g_rowptr[NNODES + 1];
__device__ int   g_csr_src[EDGES];
__device__ int   g_blockSums[128];

// ---------------- degree ----------------

__global__ void deg_kernel(const int* __restrict__ dst, int* __restrict__ deg, int e) {
    int i = blockIdx.x * blockDim.x + threadIdx.x;
    if (i < e) atomicAdd(&deg[dst[i]], 1);
}

// ---------------- exclusive prefix scan of deg -> rowptr; also dinv ----------------

__global__ __launch_bounds__(256)
void scan_block_sums(const int* __restrict__ deg, int* __restrict__ blockSums, int n) {
    __shared__ int sdata[256];
    int base = blockIdx.x * 2048;
    int tid = threadIdx.x;
    int s = 0;
#pragma unroll
    for (int j = 0; j < 8; j++) {
        int i = base + tid * 8 + j;
        if (i < n) s += deg[i];
    }
    sdata[tid] = s;
    __syncthreads();
    for (int off = 128; off; off >>= 1) {
        if (tid < off) sdata[tid] += sdata[tid + off];
        __syncthreads();
    }
    if (tid == 0) blockSums[blockIdx.x] = sdata[0];
}

// parallel exclusive scan of up to 64 block sums (one warp, 2 elems/lane)
__global__ void scan_offsets(int* __restrict__ blockSums, int nb) {
    int lane = threadIdx.x;            // 32 threads
    int v0 = (lane      < nb) ? blockSums[lane]      : 0;
    int v1 = (lane + 32 < nb) ? blockSums[lane + 32] : 0;
    int s0 = v0;
#pragma unroll
    for (int off = 1; off < 32; off <<= 1) {
        int t = __shfl_up_sync(0xFFFFFFFFu, s0, off);
        if (lane >= off) s0 += t;
    }
    int total0 = __shfl_sync(0xFFFFFFFFu, s0, 31);
    int s1 = v1;
#pragma unroll
    for (int off = 1; off < 32; off <<= 1) {
        int t = __shfl_up_sync(0xFFFFFFFFu, s1, off);
        if (lane >= off) s1 += t;
    }
    if (lane      < nb) blockSums[lane]      = s0 - v0;            // exclusive
    if (lane + 32 < nb) blockSums[lane + 32] = total0 + s1 - v1;
}

__global__ __launch_bounds__(256)
void scan_final(const int* __restrict__ deg, const int* __restrict__ blockSums,
                int* __restrict__ rowptr, float* __restrict__ dinv, int n) {
    __shared__ int tsum[256];
    int base = blockIdx.x * 2048;
    int tid = threadIdx.x;
    int loc[8];
    int dv[8];
    int s = 0;
#pragma unroll
    for (int j = 0; j < 8; j++) {
        int i = base + tid * 8 + j;
        int v = (i < n) ? deg[i] : 0;
        dv[j]  = v;
        loc[j] = s;
        s += v;
    }
    tsum[tid] = s;
    __syncthreads();
    for (int off = 1; off < 256; off <<= 1) {
        int t = (tid >= off) ? tsum[tid - off] : 0;
        __syncthreads();
        tsum[tid] += t;
        __syncthreads();
    }
    int threadOff = tsum[tid] - s;  // exclusive within block
    int cOff = blockSums[blockIdx.x];
#pragma unroll
    for (int j = 0; j < 8; j++) {
        int i = base + tid * 8 + j;
        if (i < n) {
            int rp = cOff + threadOff + loc[j];
            rowptr[i] = rp;
            dinv[i]   = rsqrtf((float)(dv[j] + 1));   // +1 self-loop
            if (i == n - 1) rowptr[n] = rp + dv[j];
        }
    }
}

// ---------------- scatter edges into CSR slots (counts deg back down to 0) ----------

__global__ void scatter_kernel(const int* __restrict__ src, const int* __restrict__ dst,
                               const int* __restrict__ rowptr, int* __restrict__ deg,
                               int* __restrict__ csr, int e) {
    int i = blockIdx.x * blockDim.x + threadIdx.x;
    if (i < e) {
        int d = dst[i];
        int pos = rowptr[d] + atomicAdd(&deg[d], -1) - 1;   // unique slot; deg ends at 0
        csr[pos] = src[i];
    }
}

// ---------------- GEMM: G[n,128] = A[n,K] @ W[K,128] (unscaled) ----------------
// 128x128 block tile, BK=16, 256 threads, 8x8 per thread, smem double-buffered.

template <int K>
__global__ __launch_bounds__(256)
void gemm_kernel(const float* __restrict__ A, const float* __restrict__ W,
                 float* __restrict__ G, int n) {
    constexpr int BM = 128, BN = 128, BK = 16;
    constexpr int APAD = 4;
    constexpr int TILES = (K + BK - 1) / BK;
    constexpr bool KV4 = (K % BK) == 0;   // vectorizable A loads (K=128)

    __shared__ float As[2][BK][BM + APAD];
    __shared__ float Bs[2][BK][BN];

    const int tid = threadIdx.x;
    const int tx  = tid & 15;
    const int ty  = tid >> 4;
    const int rowBase = blockIdx.x * BM;

    float acc[8][8];
#pragma unroll
    for (int i = 0; i < 8; i++)
#pragma unroll
        for (int j = 0; j < 8; j++) acc[i][j] = 0.f;

    auto loadA = [&](int k0, int buf) {
        if (KV4) {
#pragma unroll
            for (int j = 0; j < 2; j++) {
                int q  = tid * 2 + j;
                int r  = q >> 2;
                int kq = (q & 3) * 4;
                int gr = rowBase + r;
                float4 v = make_float4(0.f, 0.f, 0.f, 0.f);
                if (gr < n) v = *(const float4*)&A[(size_t)gr * K + k0 + kq];
                As[buf][kq + 0][r] = v.x;
                As[buf][kq + 1][r] = v.y;
                As[buf][kq + 2][r] = v.z;
                As[buf][kq + 3][r] = v.w;
            }
        } else {
#pragma unroll
            for (int j = 0; j < 8; j++) {
                int l = tid + 256 * j;
                int r = l >> 4, kk = l & 15;
                int gr = rowBase + r, gk = k0 + kk;
                float v = 0.f;
                if (gr < n && gk < K) v = A[(size_t)gr * K + gk];
                As[buf][kk][r] = v;
            }
        }
    };
    auto loadB = [&](int k0, int buf) {
#pragma unroll
        for (int j = 0; j < 8; j++) {
            int l = tid + 256 * j;
            int kk = l >> 7, nn = l & 127;
            int gk = k0 + kk;
            Bs[buf][kk][nn] = (gk < K) ? W[gk * BN + nn] : 0.f;
        }
    };

    loadA(0, 0);
    loadB(0, 0);
    __syncthreads();

    for (int t = 0; t < TILES; t++) {
        const int cur = t & 1;
        if (t + 1 < TILES) {
            loadA((t + 1) * BK, cur ^ 1);
            loadB((t + 1) * BK, cur ^ 1);
        }

#pragma unroll
        for (int kk = 0; kk < BK; kk++) {
            float4 a0 = *(const float4*)&As[cur][kk][ty * 8];
            float4 a1 = *(const float4*)&As[cur][kk][ty * 8 + 4];
            float4 b0 = *(const float4*)&Bs[cur][kk][tx * 8];
            float4 b1 = *(const float4*)&Bs[cur][kk][tx * 8 + 4];
            float ar[8] = {a0.x, a0.y, a0.z, a0.w, a1.x, a1.y, a1.z, a1.w};
            float br[8] = {b0.x, b0.y, b0.z, b0.w, b1.x, b1.y, b1.z, b1.w};
#pragma unroll
            for (int i = 0; i < 8; i++)
#pragma unroll
                for (int j = 0; j < 8; j++) acc[i][j] = fmaf(ar[i], br[j], acc[i][j]);
        }
        __syncthreads();
    }

#pragma unroll
    for (int i = 0; i < 8; i++) {
        int r = rowBase + ty * 8 + i;
        if (r < n) {
            float4 o0 = make_float4(acc[i][0], acc[i][1], acc[i][2], acc[i][3]);
            float4 o1 = make_float4(acc[i][4], acc[i][5], acc[i][6], acc[i][7]);
            size_t base = (size_t)r * BN + tx * 8;
            *(float4*)&G[base]     = o0;
            *(float4*)&G[base + 4] = o1;
        }
    }
}

// ---------------- fused aggregation: warp per node, CSR segment, no atomics --------
// EDGE_SCALE=true  (layer 1): acc = dinv[i]*g[i] + Σ dinv[s]*g[s];
//                             h' = dinv[i] * relu(dinv[i]*acc + b)   [pre-scaled for next layer]
// EDGE_SCALE=false (layer 2): acc = g[i] + Σ g[s]; h = relu(dinv[i]*acc + b)
// FINAL=true: classifier out = h @ Wc + bc (warp reduce)

template <bool EDGE_SCALE, bool FINAL>
__global__ __launch_bounds__(256)
void agg_fused_kernel(const float4* __restrict__ g, const int* __restrict__ csr,
                      const int* __restrict__ rowptr,
                      const float* __restrict__ dinv, const float4* __restrict__ bias,
                      float4* __restrict__ h,
                      const float4* __restrict__ Wc4, const float* __restrict__ bc,
                      float2* __restrict__ out, int n) {
    int node = (blockIdx.x * blockDim.x + threadIdx.x) >> 5;
    int lane = threadIdx.x & 31;
    if (node >= n) return;

    const int start = rowptr[node];
    const int end   = rowptr[node + 1];
    const int cnt   = end - start;
    const float s   = dinv[node];

    float4 a[8];
    {   // self-loop term
        float4 v = g[(size_t)node * 32 + lane];
        if (EDGE_SCALE) { v.x *= s; v.y *= s; v.z *= s; v.w *= s; }
        a[0] = v;
    }
#pragma unroll
    for (int i = 1; i < 8; i++) a[i] = make_float4(0.f, 0.f, 0.f, 0.f);

    int j = 0;
    for (; j + 8 <= cnt; j += 8) {
        int idx[8];
#pragma unroll
        for (int u = 0; u < 8; u++) idx[u] = __ldg(&csr[start + j + u]);
        float dv[8];
        if (EDGE_SCALE) {
#pragma unroll
            for (int u = 0; u < 8; u++) dv[u] = __ldg(&dinv[idx[u]]);
        }
#pragma unroll
        for (int u = 0; u < 8; u++) {
            float4 v = g[(size_t)idx[u] * 32 + lane];
            if (EDGE_SCALE) {
                a[u].x = fmaf(dv[u], v.x, a[u].x);
                a[u].y = fmaf(dv[u], v.y, a[u].y);
                a[u].z = fmaf(dv[u], v.z, a[u].z);
                a[u].w = fmaf(dv[u], v.w, a[u].w);
            } else {
                a[u].x += v.x; a[u].y += v.y; a[u].z += v.z; a[u].w += v.w;
            }
        }
    }
    if (j + 4 <= cnt) {
        int idx[4];
#pragma unroll
        for (int u = 0; u < 4; u++) idx[u] = __ldg(&csr[start + j + u]);
        float dv[4];
        if (EDGE_SCALE) {
#pragma unroll
            for (int u = 0; u < 4; u++) dv[u] = __ldg(&dinv[idx[u]]);
        }
#pragma unroll
        for (int u = 0; u < 4; u++) {
            float4 v = g[(size_t)idx[u] * 32 + lane];
            if (EDGE_SCALE) {
                a[u].x = fmaf(dv[u], v.x, a[u].x);
                a[u].y = fmaf(dv[u], v.y, a[u].y);
                a[u].z = fmaf(dv[u], v.z, a[u].z);
                a[u].w = fmaf(dv[u], v.w, a[u].w);
            } else {
                a[u].x += v.x; a[u].y += v.y; a[u].z += v.z; a[u].w += v.w;
            }
        }
        j += 4;
    }
    for (; j < cnt; j++) {
        int s0 = __ldg(&csr[start + j]);
        float4 v = g[(size_t)s0 * 32 + lane];
        if (EDGE_SCALE) {
            float d0 = __ldg(&dinv[s0]);
            a[0].x = fmaf(d0, v.x, a[0].x);
            a[0].y = fmaf(d0, v.y, a[0].y);
            a[0].z = fmaf(d0, v.z, a[0].z);
            a[0].w = fmaf(d0, v.w, a[0].w);
        } else {
            a[0].x += v.x; a[0].y += v.y; a[0].z += v.z; a[0].w += v.w;
        }
    }

    float4 acc;
    acc.x = ((a[0].x + a[1].x) + (a[2].x + a[3].x)) + ((a[4].x + a[5].x) + (a[6].x + a[7].x));
    acc.y = ((a[0].y + a[1].y) + (a[2].y + a[3].y)) + ((a[4].y + a[5].y) + (a[6].y + a[7].y));
    acc.z = ((a[0].z + a[1].z) + (a[2].z + a[3].z)) + ((a[4].z + a[5].z) + (a[6].z + a[7].z));
    acc.w = ((a[0].w + a[1].w) + (a[2].w + a[3].w)) + ((a[4].w + a[5].w) + (a[6].w + a[7].w));

    float4 bv = bias[lane];
    float4 hv;
    hv.x = fmaxf(fmaf(s, acc.x, bv.x), 0.f);
    hv.y = fmaxf(fmaf(s, acc.y, bv.y), 0.f);
    hv.z = fmaxf(fmaf(s, acc.z, bv.z), 0.f);
    hv.w = fmaxf(fmaf(s, acc.w, bv.w), 0.f);

    if (!FINAL) {
        if (EDGE_SCALE) {   // pre-scale for next layer's source role
            hv.x *= s; hv.y *= s; hv.z *= s; hv.w *= s;
        }
        h[(size_t)node * 32 + lane] = hv;
    } else {
        float4 w0 = __ldg(&Wc4[lane * 2]);
        float4 w1 = __ldg(&Wc4[lane * 2 + 1]);
        float p0 = hv.x * w0.x + hv.y * w0.z + hv.z * w1.x + hv.w * w1.z;
        float p1 = hv.x * w0.y + hv.y * w0.w + hv.z * w1.y + hv.w * w1.w;
#pragma unroll
        for (int off = 16; off; off >>= 1) {
            p0 += __shfl_xor_sync(0xFFFFFFFFu, p0, off);
            p1 += __shfl_xor_sync(0xFFFFFFFFu, p1, off);
        }
        if (lane == 0) out[node] = make_float2(p0 + bc[0], p1 + bc[1]);
    }
}

// ---------------- launch ----------------

extern "C" void kernel_launch(void* const* d_in, const int* in_sizes, int n_in,
                              void* d_out, int out_size) {
    const float* x  = (const float*)d_in[0];
    const int*   ei = (const int*)d_in[1];
    const float* W1 = (const float*)d_in[2];
    const float* b1 = (const float*)d_in[3];
    const float* W2 = (const float*)d_in[4];
    const float* b2 = (const float*)d_in[5];
    const float* Wc = (const float*)d_in[6];
    const float* bc = (const float*)d_in[7];
    float* out = (float*)d_out;

    const int n = NNODES;
    const int e = in_sizes[1] / 2;
    const int* src = ei;
    const int* dst = ei + e;

    float *G, *H, *DINV;
    int *DEG, *ROWPTR, *CSR, *BSUMS;
    cudaGetSymbolAddress((void**)&G,      g_bufG);
    cudaGetSymbolAddress((void**)&H,      g_bufH);
    cudaGetSymbolAddress((void**)&DINV,   g_dinv);
    cudaGetSymbolAddress((void**)&DEG,    g_deg);
    cudaGetSymbolAddress((void**)&ROWPTR, g_rowptr);
    cudaGetSymbolAddress((void**)&CSR,    g_csr_src);
    cudaGetSymbolAddress((void**)&BSUMS,  g_blockSums);

    // side stream + events for preprocessing overlap (host handles, created once)
    static cudaStream_t s_pre = nullptr;
    static cudaEvent_t ev_fork = nullptr, ev_pre = nullptr;
    if (!s_pre) {
        cudaStreamCreate(&s_pre);
        cudaEventCreateWithFlags(&ev_fork, cudaEventDisableTiming);
        cudaEventCreateWithFlags(&ev_pre,  cudaEventDisableTiming);
    }

    const int gemmB = (n + 127) / 128;
    const int aggB  = (int)(((long long)n * 32 + 255) / 256);
    const int scanB = (n + 2047) / 2048;

    // ---- fork: CSR build on side stream, GEMM1 on main stream ----
    cudaEventRecord(ev_fork, 0);
    cudaStreamWaitEvent(s_pre, ev_fork, 0);

    deg_kernel<<<(e + 255) / 256, 256, 0, s_pre>>>(dst, DEG, e);
    scan_block_sums<<<scanB, 256, 0, s_pre>>>(DEG, BSUMS, n);
    scan_offsets<<<1, 32, 0, s_pre>>>(BSUMS, scanB);
    scan_final<<<scanB, 256, 0, s_pre>>>(DEG, BSUMS, ROWPTR, DINV, n);
    scatter_kernel<<<(e + 255) / 256, 256, 0, s_pre>>>(src, dst, ROWPTR, DEG, CSR, e);
    cudaEventRecord(ev_pre, s_pre);

    gemm_kernel<IN_F><<<gemmB, 256>>>(x, W1, G, n);   // independent of CSR/dinv

    // ---- join, then layer 1 aggregation ----
    cudaStreamWaitEvent(0, ev_pre, 0);
    agg_fused_kernel<true, false><<<aggB, 256>>>((const float4*)G, CSR, ROWPTR, DINV,
                                                 (const float4*)b1, (float4*)H,
                                                 nullptr, nullptr, nullptr, n);

    // ---- layer 2 (+ fused classifier) ----
    gemm_kernel<HID><<<gemmB, 256>>>(H, W2, G, n);
    agg_fused_kernel<false, true><<<aggB, 256>>>((const float4*)G, CSR, ROWPTR, DINV,
                                                 (const float4*)b2, nullptr,
                                                 (const float4*)Wc, bc, (float2*)out, n);
}

// round 9
// speedup vs baseline: 1.0772x; 1.0117x over previous
#include <cuda_runtime.h>
#include <cstdint>

#define NNODES 100000
#define EDGES  1600000
#define IN_F   165
#define HID    128
#define CHUNK0 50048   // 391 * 128

// Scratch (allocation-free rule: __device__ globals)
__device__ float g_bufG[(size_t)NNODES * HID];   // layer-1 GEMM out: x@W1 (unscaled)
__device__ float g_bufG2[(size_t)NNODES * HID];  // layer-2 GEMM out: H@W2 (unscaled)
__device__ float g_bufH[(size_t)NNODES * HID];   // layer-1 activation, pre-scaled by dinv
__device__ int   g_deg[NNODES];                  // self-restoring: scatter counts it back to 0
__device__ float g_dinv[NNODES];
__device__ int   g_rowptr[NNODES + 1];
__device__ int   g_csr_src[EDGES];
__device__ int   g_blockSums[128];

// ---------------- degree ----------------

__global__ void deg_kernel(const int* __restrict__ dst, int* __restrict__ deg, int e) {
    int i = blockIdx.x * blockDim.x + threadIdx.x;
    if (i < e) atomicAdd(&deg[dst[i]], 1);
}

// ---------------- exclusive prefix scan of deg -> rowptr; also dinv ----------------

__global__ __launch_bounds__(256)
void scan_block_sums(const int* __restrict__ deg, int* __restrict__ blockSums, int n) {
    __shared__ int sdata[256];
    int base = blockIdx.x * 2048;
    int tid = threadIdx.x;
    int s = 0;
#pragma unroll
    for (int j = 0; j < 8; j++) {
        int i = base + tid * 8 + j;
        if (i < n) s += deg[i];
    }
    sdata[tid] = s;
    __syncthreads();
    for (int off = 128; off; off >>= 1) {
        if (tid < off) sdata[tid] += sdata[tid + off];
        __syncthreads();
    }
    if (tid == 0) blockSums[blockIdx.x] = sdata[0];
}

__global__ void scan_offsets(int* __restrict__ blockSums, int nb) {
    int lane = threadIdx.x;            // 32 threads
    int v0 = (lane      < nb) ? blockSums[lane]      : 0;
    int v1 = (lane + 32 < nb) ? blockSums[lane + 32] : 0;
    int s0 = v0;
#pragma unroll
    for (int off = 1; off < 32; off <<= 1) {
        int t = __shfl_up_sync(0xFFFFFFFFu, s0, off);
        if (lane >= off) s0 += t;
    }
    int total0 = __shfl_sync(0xFFFFFFFFu, s0, 31);
    int s1 = v1;
#pragma unroll
    for (int off = 1; off < 32; off <<= 1) {
        int t = __shfl_up_sync(0xFFFFFFFFu, s1, off);
        if (lane >= off) s1 += t;
    }
    if (lane      < nb) blockSums[lane]      = s0 - v0;            // exclusive
    if (lane + 32 < nb) blockSums[lane + 32] = total0 + s1 - v1;
}

__global__ __launch_bounds__(256)
void scan_final(const int* __restrict__ deg, const int* __restrict__ blockSums,
                int* __restrict__ rowptr, float* __restrict__ dinv, int n) {
    __shared__ int tsum[256];
    int base = blockIdx.x * 2048;
    int tid = threadIdx.x;
    int loc[8];
    int dv[8];
    int s = 0;
#pragma unroll
    for (int j = 0; j < 8; j++) {
        int i = base + tid * 8 + j;
        int v = (i < n) ? deg[i] : 0;
        dv[j]  = v;
        loc[j] = s;
        s += v;
    }
    tsum[tid] = s;
    __syncthreads();
    for (int off = 1; off < 256; off <<= 1) {
        int t = (tid >= off) ? tsum[tid - off] : 0;
        __syncthreads();
        tsum[tid] += t;
        __syncthreads();
    }
    int threadOff = tsum[tid] - s;  // exclusive within block
    int cOff = blockSums[blockIdx.x];
#pragma unroll
    for (int j = 0; j < 8; j++) {
        int i = base + tid * 8 + j;
        if (i < n) {
            int rp = cOff + threadOff + loc[j];
            rowptr[i] = rp;
            dinv[i]   = rsqrtf((float)(dv[j] + 1));   // +1 self-loop
            if (i == n - 1) rowptr[n] = rp + dv[j];
        }
    }
}

// ---------------- scatter edges into CSR slots (counts deg back down to 0) ----------

__global__ void scatter_kernel(const int* __restrict__ src, const int* __restrict__ dst,
                               const int* __restrict__ rowptr, int* __restrict__ deg,
                               int* __restrict__ csr, int e) {
    int i = blockIdx.x * blockDim.x + threadIdx.x;
    if (i < e) {
        int d = dst[i];
        int pos = rowptr[d] + atomicAdd(&deg[d], -1) - 1;   // unique slot; deg ends at 0
        csr[pos] = src[i];
    }
}

// ---------------- GEMM: G[r0..n1,128] = A[r0..n1,K] @ W[K,128] (unscaled) ----------
// 128x128 block tile, BK=16, 256 threads, 8x8 per thread, smem double-buffered.

template <int K>
__global__ __launch_bounds__(256)
void gemm_kernel(const float* __restrict__ A, const float* __restrict__ W,
                 float* __restrict__ G, int row0, int n1) {
    constexpr int BM = 128, BN = 128, BK = 16;
    constexpr int APAD = 4;
    constexpr int TILES = (K + BK - 1) / BK;
    constexpr bool KV4 = (K % BK) == 0;   // vectorizable A loads (K=128)

    __shared__ float As[2][BK][BM + APAD];
    __shared__ float Bs[2][BK][BN];

    const int tid = threadIdx.x;
    const int tx  = tid & 15;
    const int ty  = tid >> 4;
    const int rowBase = row0 + blockIdx.x * BM;

    float acc[8][8];
#pragma unroll
    for (int i = 0; i < 8; i++)
#pragma unroll
        for (int j = 0; j < 8; j++) acc[i][j] = 0.f;

    auto loadA = [&](int k0, int buf) {
        if (KV4) {
#pragma unroll
            for (int j = 0; j < 2; j++) {
                int q  = tid * 2 + j;
                int r  = q >> 2;
                int kq = (q & 3) * 4;
                int gr = rowBase + r;
                float4 v = make_float4(0.f, 0.f, 0.f, 0.f);
                if (gr < n1) v = *(const float4*)&A[(size_t)gr * K + k0 + kq];
                As[buf][kq + 0][r] = v.x;
                As[buf][kq + 1][r] = v.y;
                As[buf][kq + 2][r] = v.z;
                As[buf][kq + 3][r] = v.w;
            }
        } else {
#pragma unroll
            for (int j = 0; j < 8; j++) {
                int l = tid + 256 * j;
                int r = l >> 4, kk = l & 15;
                int gr = rowBase + r, gk = k0 + kk;
                float v = 0.f;
                if (gr < n1 && gk < K) v = A[(size_t)gr * K + gk];
                As[buf][kk][r] = v;
            }
        }
    };
    auto loadB = [&](int k0, int buf) {
#pragma unroll
        for (int j = 0; j < 8; j++) {
            int l = tid + 256 * j;
            int kk = l >> 7, nn = l & 127;
            int gk = k0 + kk;
            Bs[buf][kk][nn] = (gk < K) ? W[gk * BN + nn] : 0.f;
        }
    };

    loadA(0, 0);
    loadB(0, 0);
    __syncthreads();

    for (int t = 0; t < TILES; t++) {
        const int cur = t & 1;
        if (t + 1 < TILES) {
            loadA((t + 1) * BK, cur ^ 1);
            loadB((t + 1) * BK, cur ^ 1);
        }

#pragma unroll
        for (int kk = 0; kk < BK; kk++) {
            float4 a0 = *(const float4*)&As[cur][kk][ty * 8];
            float4 a1 = *(const float4*)&As[cur][kk][ty * 8 + 4];
            float4 b0 = *(const float4*)&Bs[cur][kk][tx * 8];
            float4 b1 = *(const float4*)&Bs[cur][kk][tx * 8 + 4];
            float ar[8] = {a0.x, a0.y, a0.z, a0.w, a1.x, a1.y, a1.z, a1.w};
            float br[8] = {b0.x, b0.y, b0.z, b0.w, b1.x, b1.y, b1.z, b1.w};
#pragma unroll
            for (int i = 0; i < 8; i++)
#pragma unroll
                for (int j = 0; j < 8; j++) acc[i][j] = fmaf(ar[i], br[j], acc[i][j]);
        }
        __syncthreads();
    }

#pragma unroll
    for (int i = 0; i < 8; i++) {
        int r = rowBase + ty * 8 + i;
        if (r < n1) {
            float4 o0 = make_float4(acc[i][0], acc[i][1], acc[i][2], acc[i][3]);
            float4 o1 = make_float4(acc[i][4], acc[i][5], acc[i][6], acc[i][7]);
            size_t base = (size_t)r * BN + tx * 8;
            *(float4*)&G[base]     = o0;
            *(float4*)&G[base + 4] = o1;
        }
    }
}

// ---------------- fused aggregation: warp per node in [n0,n1), CSR, no atomics --------
// EDGE_SCALE=true  (layer 1): acc = dinv[i]*g[i] + Σ dinv[s]*g[s];
//                             h' = dinv[i] * relu(dinv[i]*acc + b)   [pre-scaled for layer 2]
// EDGE_SCALE=false (layer 2): acc = g[i] + Σ g[s]; h = relu(dinv[i]*acc + b)
// FINAL=true: classifier out = h @ Wc + bc (warp reduce)

template <bool EDGE_SCALE, bool FINAL>
__global__ __launch_bounds__(256)
void agg_fused_kernel(const float4* __restrict__ g, const int* __restrict__ csr,
                      const int* __restrict__ rowptr,
                      const float* __restrict__ dinv, const float4* __restrict__ bias,
                      float4* __restrict__ h,
                      const float4* __restrict__ Wc4, const float* __restrict__ bc,
                      float2* __restrict__ out, int n0, int n1) {
    int node = n0 + ((blockIdx.x * blockDim.x + threadIdx.x) >> 5);
    int lane = threadIdx.x & 31;
    if (node >= n1) return;

    const int start = rowptr[node];
    const int end   = rowptr[node + 1];
    const int cnt   = end - start;
    const float s   = dinv[node];

    float4 a[8];
    {   // self-loop term
        float4 v = g[(size_t)node * 32 + lane];
        if (EDGE_SCALE) { v.x *= s; v.y *= s; v.z *= s; v.w *= s; }
        a[0] = v;
    }
#pragma unroll
    for (int i = 1; i < 8; i++) a[i] = make_float4(0.f, 0.f, 0.f, 0.f);

    int j = 0;
    for (; j + 8 <= cnt; j += 8) {
        int idx[8];
#pragma unroll
        for (int u = 0; u < 8; u++) idx[u] = __ldg(&csr[start + j + u]);
        float dv[8];
        if (EDGE_SCALE) {
#pragma unroll
            for (int u = 0; u < 8; u++) dv[u] = __ldg(&dinv[idx[u]]);
        }
#pragma unroll
        for (int u = 0; u < 8; u++) {
            float4 v = g[(size_t)idx[u] * 32 + lane];
            if (EDGE_SCALE) {
                a[u].x = fmaf(dv[u], v.x, a[u].x);
                a[u].y = fmaf(dv[u], v.y, a[u].y);
                a[u].z = fmaf(dv[u], v.z, a[u].z);
                a[u].w = fmaf(dv[u], v.w, a[u].w);
            } else {
                a[u].x += v.x; a[u].y += v.y; a[u].z += v.z; a[u].w += v.w;
            }
        }
    }
    if (j + 4 <= cnt) {
        int idx[4];
#pragma unroll
        for (int u = 0; u < 4; u++) idx[u] = __ldg(&csr[start + j + u]);
        float dv[4];
        if (EDGE_SCALE) {
#pragma unroll
            for (int u = 0; u < 4; u++) dv[u] = __ldg(&dinv[idx[u]]);
        }
#pragma unroll
        for (int u = 0; u < 4; u++) {
            float4 v = g[(size_t)idx[u] * 32 + lane];
            if (EDGE_SCALE) {
                a[u].x = fmaf(dv[u], v.x, a[u].x);
                a[u].y = fmaf(dv[u], v.y, a[u].y);
                a[u].z = fmaf(dv[u], v.z, a[u].z);
                a[u].w = fmaf(dv[u], v.w, a[u].w);
            } else {
                a[u].x += v.x; a[u].y += v.y; a[u].z += v.z; a[u].w += v.w;
            }
        }
        j += 4;
    }
    for (; j < cnt; j++) {
        int s0 = __ldg(&csr[start + j]);
        float4 v = g[(size_t)s0 * 32 + lane];
        if (EDGE_SCALE) {
            float d0 = __ldg(&dinv[s0]);
            a[0].x = fmaf(d0, v.x, a[0].x);
            a[0].y = fmaf(d0, v.y, a[0].y);
            a[0].z = fmaf(d0, v.z, a[0].z);
            a[0].w = fmaf(d0, v.w, a[0].w);
        } else {
            a[0].x += v.x; a[0].y += v.y; a[0].z += v.z; a[0].w += v.w;
        }
    }

    float4 acc;
    acc.x = ((a[0].x + a[1].x) + (a[2].x + a[3].x)) + ((a[4].x + a[5].x) + (a[6].x + a[7].x));
    acc.y = ((a[0].y + a[1].y) + (a[2].y + a[3].y)) + ((a[4].y + a[5].y) + (a[6].y + a[7].y));
    acc.z = ((a[0].z + a[1].z) + (a[2].z + a[3].z)) + ((a[4].z + a[5].z) + (a[6].z + a[7].z));
    acc.w = ((a[0].w + a[1].w) + (a[2].w + a[3].w)) + ((a[4].w + a[5].w) + (a[6].w + a[7].w));

    float4 bv = bias[lane];
    float4 hv;
    hv.x = fmaxf(fmaf(s, acc.x, bv.x), 0.f);
    hv.y = fmaxf(fmaf(s, acc.y, bv.y), 0.f);
    hv.z = fmaxf(fmaf(s, acc.z, bv.z), 0.f);
    hv.w = fmaxf(fmaf(s, acc.w, bv.w), 0.f);

    if (!FINAL) {
        if (EDGE_SCALE) {   // pre-scale for next layer's source role
            hv.x *= s; hv.y *= s; hv.z *= s; hv.w *= s;
        }
        h[(size_t)node * 32 + lane] = hv;
    } else {
        float4 w0 = __ldg(&Wc4[lane * 2]);
        float4 w1 = __ldg(&Wc4[lane * 2 + 1]);
        float p0 = hv.x * w0.x + hv.y * w0.z + hv.z * w1.x + hv.w * w1.z;
        float p1 = hv.x * w0.y + hv.y * w0.w + hv.z * w1.y + hv.w * w1.w;
#pragma unroll
        for (int off = 16; off; off >>= 1) {
            p0 += __shfl_xor_sync(0xFFFFFFFFu, p0, off);
            p1 += __shfl_xor_sync(0xFFFFFFFFu, p1, off);
        }
        if (lane == 0) out[node] = make_float2(p0 + bc[0], p1 + bc[1]);
    }
}

// ---------------- launch ----------------

extern "C" void kernel_launch(void* const* d_in, const int* in_sizes, int n_in,
                              void* d_out, int out_size) {
    const float* x  = (const float*)d_in[0];
    const int*   ei = (const int*)d_in[1];
    const float* W1 = (const float*)d_in[2];
    const float* b1 = (const float*)d_in[3];
    const float* W2 = (const float*)d_in[4];
    const float* b2 = (const float*)d_in[5];
    const float* Wc = (const float*)d_in[6];
    const float* bc = (const float*)d_in[7];
    float* out = (float*)d_out;

    const int n = NNODES;
    const int e = in_sizes[1] / 2;
    const int* src = ei;
    const int* dst = ei + e;

    float *G, *G2, *H, *DINV;
    int *DEG, *ROWPTR, *CSR, *BSUMS;
    cudaGetSymbolAddress((void**)&G,      g_bufG);
    cudaGetSymbolAddress((void**)&G2,     g_bufG2);
    cudaGetSymbolAddress((void**)&H,      g_bufH);
    cudaGetSymbolAddress((void**)&DINV,   g_dinv);
    cudaGetSymbolAddress((void**)&DEG,    g_deg);
    cudaGetSymbolAddress((void**)&ROWPTR, g_rowptr);
    cudaGetSymbolAddress((void**)&CSR,    g_csr_src);
    cudaGetSymbolAddress((void**)&BSUMS,  g_blockSums);

    // side stream + events (host handles, created once)
    static cudaStream_t s_side = nullptr;
    static cudaEvent_t ev_fork = nullptr, ev_pre = nullptr, ev_a0 = nullptr, ev_a1 = nullptr;
    if (!s_side) {
        cudaStreamCreate(&s_side);
        cudaEventCreateWithFlags(&ev_fork, cudaEventDisableTiming);
        cudaEventCreateWithFlags(&ev_pre,  cudaEventDisableTiming);
        cudaEventCreateWithFlags(&ev_a0,   cudaEventDisableTiming);
        cudaEventCreateWithFlags(&ev_a1,   cudaEventDisableTiming);
    }

    const int c0 = CHUNK0;                       // chunk split (multiple of 128)
    const int gemmB_full = (n + 127) / 128;
    const int gemmB_c0   = c0 / 128;
    const int gemmB_c1   = (n - c0 + 127) / 128;
    const int aggB_full  = (int)(((long long)n * 32 + 255) / 256);
    const int aggB_c0    = (int)(((long long)c0 * 32 + 255) / 256);
    const int aggB_c1    = (int)(((long long)(n - c0) * 32 + 255) / 256);
    const int scanB      = (n + 2047) / 2048;

    // ---- fork: CSR build on side stream, GEMM1 on main stream ----
    cudaEventRecord(ev_fork, 0);
    cudaStreamWaitEvent(s_side, ev_fork, 0);

    deg_kernel<<<(e + 255) / 256, 256, 0, s_side>>>(dst, DEG, e);
    scan_block_sums<<<scanB, 256, 0, s_side>>>(DEG, BSUMS, n);
    scan_offsets<<<1, 32, 0, s_side>>>(BSUMS, scanB);
    scan_final<<<scanB, 256, 0, s_side>>>(DEG, BSUMS, ROWPTR, DINV, n);
    scatter_kernel<<<(e + 255) / 256, 256, 0, s_side>>>(src, dst, ROWPTR, DEG, CSR, e);
    cudaEventRecord(ev_pre, s_side);

    gemm_kernel<IN_F><<<gemmB_full, 256>>>(x, W1, G, 0, n);   // independent of CSR/dinv

    // ---- join preprocessing, then pipelined agg1 / GEMM2 ----
    cudaStreamWaitEvent(0, ev_pre, 0);

    // agg1 chunk 0 on main (reads G, writes H[0,c0))
    agg_fused_kernel<true, false><<<aggB_c0, 256>>>((const float4*)G, CSR, ROWPTR, DINV,
                                                    (const float4*)b1, (float4*)H,
                                                    nullptr, nullptr, nullptr, 0, c0);
    cudaEventRecord(ev_a0, 0);

    // agg1 chunk 1 on side (reads G, writes H[c0,n)) — concurrent with GEMM2 chunk 0
    cudaStreamWaitEvent(s_side, ev_a0, 0);
    agg_fused_kernel<true, false><<<aggB_c1, 256, 0, s_side>>>((const float4*)G, CSR, ROWPTR, DINV,
                                                               (const float4*)b1, (float4*)H,
                                                               nullptr, nullptr, nullptr, c0, n);
    cudaEventRecord(ev_a1, s_side);

    // GEMM2 chunk 0 on main: reads H[0,c0), writes G2[0,c0) — disjoint from concurrent agg1(C1)
    gemm_kernel<HID><<<gemmB_c0, 256>>>(H, W2, G2, 0, c0);

    // GEMM2 chunk 1 after agg1(C1) completes
    cudaStreamWaitEvent(0, ev_a1, 0);
    gemm_kernel<HID><<<gemmB_c1, 256>>>(H, W2, G2, c0, n);

    // ---- layer 2 aggregation + fused classifier (reads full G2) ----
    agg_fused_kernel<false, true><<<aggB_full, 256>>>((const float4*)G2, CSR, ROWPTR, DINV,
                                                      (const float4*)b2, nullptr,
                                                      (const float4*)Wc, bc, (float2*)out, 0, n);
}

// round 10
// speedup vs baseline: 1.0831x; 1.0055x over previous
#include <cuda_runtime.h>
#include <cstdint>

#define NNODES 100000
#define EDGES  1600000
#define IN_F   165
#define HID    128
#define CHUNK0 50048   // 391 * 128

// Scratch (allocation-free rule: __device__ globals)
__device__ float g_bufG[(size_t)NNODES * HID];   // layer-1 GEMM out: x@W1 (unscaled)
__device__ float g_bufG2[(size_t)NNODES * HID];  // layer-2 GEMM out: H@W2 (unscaled)
__device__ float g_bufH[(size_t)NNODES * HID];   // layer-1 activation, pre-scaled by dinv
__device__ int   g_deg[NNODES];                  // self-restoring: scatter counts it back to 0
__device__ float g_dinv[NNODES];
__device__ int   g_rowptr[NNODES + 1];
__device__ int   g_csr_src[EDGES];
__device__ int   g_blockSums[128];

// ---------------- f32x2 packed helpers (sm_103a FFMA2) ----------------

typedef unsigned long long u64;

__device__ __forceinline__ u64 pack2(float lo, float hi) {
    u64 r;
    asm("mov.b64 %0, {%1, %2};" : "=l"(r) : "r"(__float_as_uint(lo)), "r"(__float_as_uint(hi)));
    return r;
}
__device__ __forceinline__ void fma2(u64& d, u64 a, u64 b) {
    asm("fma.rn.f32x2 %0, %1, %2, %3;" : "=l"(d) : "l"(a), "l"(b), "l"(d));
}
__device__ __forceinline__ void unpack2(float& lo, float& hi, u64 v) {
    uint32_t l, h;
    asm("mov.b64 {%0, %1}, %2;" : "=r"(l), "=r"(h) : "l"(v));
    lo = __uint_as_float(l);
    hi = __uint_as_float(h);
}

// ---------------- degree ----------------

__global__ void deg_kernel(const int* __restrict__ dst, int* __restrict__ deg, int e) {
    int i = blockIdx.x * blockDim.x + threadIdx.x;
    if (i < e) atomicAdd(&deg[dst[i]], 1);
}

// ---------------- exclusive prefix scan of deg -> rowptr; also dinv ----------------

__global__ __launch_bounds__(256)
void scan_block_sums(const int* __restrict__ deg, int* __restrict__ blockSums, int n) {
    __shared__ int sdata[256];
    int base = blockIdx.x * 2048;
    int tid = threadIdx.x;
    int s = 0;
#pragma unroll
    for (int j = 0; j < 8; j++) {
        int i = base + tid * 8 + j;
        if (i < n) s += deg[i];
    }
    sdata[tid] = s;
    __syncthreads();
    for (int off = 128; off; off >>= 1) {
        if (tid < off) sdata[tid] += sdata[tid + off];
        __syncthreads();
    }
    if (tid == 0) blockSums[blockIdx.x] = sdata[0];
}

__global__ void scan_offsets(int* __restrict__ blockSums, int nb) {
    int lane = threadIdx.x;            // 32 threads
    int v0 = (lane      < nb) ? blockSums[lane]      : 0;
    int v1 = (lane + 32 < nb) ? blockSums[lane + 32] : 0;
    int s0 = v0;
#pragma unroll
    for (int off = 1; off < 32; off <<= 1) {
        int t = __shfl_up_sync(0xFFFFFFFFu, s0, off);
        if (lane >= off) s0 += t;
    }
    int total0 = __shfl_sync(0xFFFFFFFFu, s0, 31);
    int s1 = v1;
#pragma unroll
    for (int off = 1; off < 32; off <<= 1) {
        int t = __shfl_up_sync(0xFFFFFFFFu, s1, off);
        if (lane >= off) s1 += t;
    }
    if (lane      < nb) blockSums[lane]      = s0 - v0;            // exclusive
    if (lane + 32 < nb) blockSums[lane + 32] = total0 + s1 - v1;
}

__global__ __launch_bounds__(256)
void scan_final(const int* __restrict__ deg, const int* __restrict__ blockSums,
                int* __restrict__ rowptr, float* __restrict__ dinv, int n) {
    __shared__ int tsum[256];
    int base = blockIdx.x * 2048;
    int tid = threadIdx.x;
    int loc[8];
    int dv[8];
    int s = 0;
#pragma unroll
    for (int j = 0; j < 8; j++) {
        int i = base + tid * 8 + j;
        int v = (i < n) ? deg[i] : 0;
        dv[j]  = v;
        loc[j] = s;
        s += v;
    }
    tsum[tid] = s;
    __syncthreads();
    for (int off = 1; off < 256; off <<= 1) {
        int t = (tid >= off) ? tsum[tid - off] : 0;
        __syncthreads();
        tsum[tid] += t;
        __syncthreads();
    }
    int threadOff = tsum[tid] - s;  // exclusive within block
    int cOff = blockSums[blockIdx.x];
#pragma unroll
    for (int j = 0; j < 8; j++) {
        int i = base + tid * 8 + j;
        if (i < n) {
            int rp = cOff + threadOff + loc[j];
            rowptr[i] = rp;
            dinv[i]   = rsqrtf((float)(dv[j] + 1));   // +1 self-loop
            if (i == n - 1) rowptr[n] = rp + dv[j];
        }
    }
}

// ---------------- scatter edges into CSR slots (counts deg back down to 0) ----------

__global__ void scatter_kernel(const int* __restrict__ src, const int* __restrict__ dst,
                               const int* __restrict__ rowptr, int* __restrict__ deg,
                               int* __restrict__ csr, int e) {
    int i = blockIdx.x * blockDim.x + threadIdx.x;
    if (i < e) {
        int d = dst[i];
        int pos = rowptr[d] + atomicAdd(&deg[d], -1) - 1;   // unique slot; deg ends at 0
        csr[pos] = src[i];
    }
}

// ---------------- GEMM: G[r0..n1,128] = A[r0..n1,K] @ W[K,128] (unscaled) ----------
// 128x128 block tile, BK=16, 256 threads, 8x8 per thread, smem double-buffered.
// Inner loop uses packed fma.rn.f32x2: accumulators hold row-pairs in 64-bit regs.

template <int K>
__global__ __launch_bounds__(256)
void gemm_kernel(const float* __restrict__ A, const float* __restrict__ W,
                 float* __restrict__ G, int row0, int n1) {
    constexpr int BM = 128, BN = 128, BK = 16;
    constexpr int APAD = 4;
    constexpr int TILES = (K + BK - 1) / BK;
    constexpr bool KV4 = (K % BK) == 0;   // vectorizable A loads (K=128)

    __shared__ __align__(16) float As[2][BK][BM + APAD];
    __shared__ __align__(16) float Bs[2][BK][BN];

    const int tid = threadIdx.x;
    const int tx  = tid & 15;
    const int ty  = tid >> 4;
    const int rowBase = row0 + blockIdx.x * BM;

    // acc2[mi][j]: rows (ty*8+2mi, ty*8+2mi+1), col tx*8+j, packed f32x2
    u64 acc2[4][8];
#pragma unroll
    for (int mi = 0; mi < 4; mi++)
#pragma unroll
        for (int j = 0; j < 8; j++) acc2[mi][j] = 0ull;

    auto loadA = [&](int k0, int buf) {
        if (KV4) {
#pragma unroll
            for (int j = 0; j < 2; j++) {
                int q  = tid * 2 + j;
                int r  = q >> 2;
                int kq = (q & 3) * 4;
                int gr = rowBase + r;
                float4 v = make_float4(0.f, 0.f, 0.f, 0.f);
                if (gr < n1) v = *(const float4*)&A[(size_t)gr * K + k0 + kq];
                As[buf][kq + 0][r] = v.x;
                As[buf][kq + 1][r] = v.y;
                As[buf][kq + 2][r] = v.z;
                As[buf][kq + 3][r] = v.w;
            }
        } else {
#pragma unroll
            for (int j = 0; j < 8; j++) {
                int l = tid + 256 * j;
                int r = l >> 4, kk = l & 15;
                int gr = rowBase + r, gk = k0 + kk;
                float v = 0.f;
                if (gr < n1 && gk < K) v = A[(size_t)gr * K + gk];
                As[buf][kk][r] = v;
            }
        }
    };
    auto loadB = [&](int k0, int buf) {
#pragma unroll
        for (int j = 0; j < 8; j++) {
            int l = tid + 256 * j;
            int kk = l >> 7, nn = l & 127;
            int gk = k0 + kk;
            Bs[buf][kk][nn] = (gk < K) ? W[gk * BN + nn] : 0.f;
        }
    };

    loadA(0, 0);
    loadB(0, 0);
    __syncthreads();

    for (int t = 0; t < TILES; t++) {
        const int cur = t & 1;
        if (t + 1 < TILES) {
            loadA((t + 1) * BK, cur ^ 1);
            loadB((t + 1) * BK, cur ^ 1);
        }

#pragma unroll
        for (int kk = 0; kk < BK; kk++) {
            // A fragment: 8 rows = 4 packed pairs, loaded as two 16B LDS
            ulonglong2 a01 = *(const ulonglong2*)&As[cur][kk][ty * 8];
            ulonglong2 a23 = *(const ulonglong2*)&As[cur][kk][ty * 8 + 4];
            u64 a2[4] = {a01.x, a01.y, a23.x, a23.y};
            // B fragment: 8 cols, duplicated into f32x2 lanes
            float4 b0 = *(const float4*)&Bs[cur][kk][tx * 8];
            float4 b1 = *(const float4*)&Bs[cur][kk][tx * 8 + 4];
            u64 bd[8];
            bd[0] = pack2(b0.x, b0.x); bd[1] = pack2(b0.y, b0.y);
            bd[2] = pack2(b0.z, b0.z); bd[3] = pack2(b0.w, b0.w);
            bd[4] = pack2(b1.x, b1.x); bd[5] = pack2(b1.y, b1.y);
            bd[6] = pack2(b1.z, b1.z); bd[7] = pack2(b1.w, b1.w);
#pragma unroll
            for (int mi = 0; mi < 4; mi++)
#pragma unroll
                for (int j = 0; j < 8; j++) fma2(acc2[mi][j], a2[mi], bd[j]);
        }
        __syncthreads();
    }

    // epilogue: unpack row pairs, store
#pragma unroll
    for (int mi = 0; mi < 4; mi++) {
        int r0 = rowBase + ty * 8 + 2 * mi;
        int r1 = r0 + 1;
        float lo[8], hi[8];
#pragma unroll
        for (int j = 0; j < 8; j++) unpack2(lo[j], hi[j], acc2[mi][j]);
        if (r0 < n1) {
            size_t base = (size_t)r0 * BN + tx * 8;
            *(float4*)&G[base]     = make_float4(lo[0], lo[1], lo[2], lo[3]);
            *(float4*)&G[base + 4] = make_float4(lo[4], lo[5], lo[6], lo[7]);
        }
        if (r1 < n1) {
            size_t base = (size_t)r1 * BN + tx * 8;
            *(float4*)&G[base]     = make_float4(hi[0], hi[1], hi[2], hi[3]);
            *(float4*)&G[base + 4] = make_float4(hi[4], hi[5], hi[6], hi[7]);
        }
    }
}

// ---------------- fused aggregation: warp per node in [n0,n1), CSR, no atomics --------
// EDGE_SCALE=true  (layer 1): acc = dinv[i]*g[i] + Σ dinv[s]*g[s];
//                             h' = dinv[i] * relu(dinv[i]*acc + b)   [pre-scaled for layer 2]
// EDGE_SCALE=false (layer 2): acc = g[i] + Σ g[s]; h = relu(dinv[i]*acc + b)
// FINAL=true: classifier out = h @ Wc + bc (warp reduce)

template <bool EDGE_SCALE, bool FINAL>
__global__ __launch_bounds__(256)
void agg_fused_kernel(const float4* __restrict__ g, const int* __restrict__ csr,
                      const int* __restrict__ rowptr,
                      const float* __restrict__ dinv, const float4* __restrict__ bias,
                      float4* __restrict__ h,
                      const float4* __restrict__ Wc4, const float* __restrict__ bc,
                      float2* __restrict__ out, int n0, int n1) {
    int node = n0 + ((blockIdx.x * blockDim.x + threadIdx.x) >> 5);
    int lane = threadIdx.x & 31;
    if (node >= n1) return;

    const int start = rowptr[node];
    const int end   = rowptr[node + 1];
    const int cnt   = end - start;
    const float s   = dinv[node];

    float4 a[8];
    {   // self-loop term
        float4 v = g[(size_t)node * 32 + lane];
        if (EDGE_SCALE) { v.x *= s; v.y *= s; v.z *= s; v.w *= s; }
        a[0] = v;
    }
#pragma unroll
    for (int i = 1; i < 8; i++) a[i] = make_float4(0.f, 0.f, 0.f, 0.f);

    int j = 0;
    for (; j + 8 <= cnt; j += 8) {
        int idx[8];
#pragma unroll
        for (int u = 0; u < 8; u++) idx[u] = __ldg(&csr[start + j + u]);
        float dv[8];
        if (EDGE_SCALE) {
#pragma unroll
            for (int u = 0; u < 8; u++) dv[u] = __ldg(&dinv[idx[u]]);
        }
#pragma unroll
        for (int u = 0; u < 8; u++) {
            float4 v = g[(size_t)idx[u] * 32 + lane];
            if (EDGE_SCALE) {
                a[u].x = fmaf(dv[u], v.x, a[u].x);
                a[u].y = fmaf(dv[u], v.y, a[u].y);
                a[u].z = fmaf(dv[u], v.z, a[u].z);
                a[u].w = fmaf(dv[u], v.w, a[u].w);
            } else {
                a[u].x += v.x; a[u].y += v.y; a[u].z += v.z; a[u].w += v.w;
            }
        }
    }
    if (j + 4 <= cnt) {
        int idx[4];
#pragma unroll
        for (int u = 0; u < 4; u++) idx[u] = __ldg(&csr[start + j + u]);
        float dv[4];
        if (EDGE_SCALE) {
#pragma unroll
            for (int u = 0; u < 4; u++) dv[u] = __ldg(&dinv[idx[u]]);
        }
#pragma unroll
        for (int u = 0; u < 4; u++) {
            float4 v = g[(size_t)idx[u] * 32 + lane];
            if (EDGE_SCALE) {
                a[u].x = fmaf(dv[u], v.x, a[u].x);
                a[u].y = fmaf(dv[u], v.y, a[u].y);
                a[u].z = fmaf(dv[u], v.z, a[u].z);
                a[u].w = fmaf(dv[u], v.w, a[u].w);
            } else {
                a[u].x += v.x; a[u].y += v.y; a[u].z += v.z; a[u].w += v.w;
            }
        }
        j += 4;
    }
    for (; j < cnt; j++) {
        int s0 = __ldg(&csr[start + j]);
        float4 v = g[(size_t)s0 * 32 + lane];
        if (EDGE_SCALE) {
            float d0 = __ldg(&dinv[s0]);
            a[0].x = fmaf(d0, v.x, a[0].x);
            a[0].y = fmaf(d0, v.y, a[0].y);
            a[0].z = fmaf(d0, v.z, a[0].z);
            a[0].w = fmaf(d0, v.w, a[0].w);
        } else {
            a[0].x += v.x; a[0].y += v.y; a[0].z += v.z; a[0].w += v.w;
        }
    }

    float4 acc;
    acc.x = ((a[0].x + a[1].x) + (a[2].x + a[3].x)) + ((a[4].x + a[5].x) + (a[6].x + a[7].x));
    acc.y = ((a[0].y + a[1].y) + (a[2].y + a[3].y)) + ((a[4].y + a[5].y) + (a[6].y + a[7].y));
    acc.z = ((a[0].z + a[1].z) + (a[2].z + a[3].z)) + ((a[4].z + a[5].z) + (a[6].z + a[7].z));
    acc.w = ((a[0].w + a[1].w) + (a[2].w + a[3].w)) + ((a[4].w + a[5].w) + (a[6].w + a[7].w));

    float4 bv = bias[lane];
    float4 hv;
    hv.x = fmaxf(fmaf(s, acc.x, bv.x), 0.f);
    hv.y = fmaxf(fmaf(s, acc.y, bv.y), 0.f);
    hv.z = fmaxf(fmaf(s, acc.z, bv.z), 0.f);
    hv.w = fmaxf(fmaf(s, acc.w, bv.w), 0.f);

    if (!FINAL) {
        if (EDGE_SCALE) {   // pre-scale for next layer's source role
            hv.x *= s; hv.y *= s; hv.z *= s; hv.w *= s;
        }
        h[(size_t)node * 32 + lane] = hv;
    } else {
        float4 w0 = __ldg(&Wc4[lane * 2]);
        float4 w1 = __ldg(&Wc4[lane * 2 + 1]);
        float p0 = hv.x * w0.x + hv.y * w0.z + hv.z * w1.x + hv.w * w1.z;
        float p1 = hv.x * w0.y + hv.y * w0.w + hv.z * w1.y + hv.w * w1.w;
#pragma unroll
        for (int off = 16; off; off >>= 1) {
            p0 += __shfl_xor_sync(0xFFFFFFFFu, p0, off);
            p1 += __shfl_xor_sync(0xFFFFFFFFu, p1, off);
        }
        if (lane == 0) out[node] = make_float2(p0 + bc[0], p1 + bc[1]);
    }
}

// ---------------- launch ----------------

extern "C" void kernel_launch(void* const* d_in, const int* in_sizes, int n_in,
                              void* d_out, int out_size) {
    const float* x  = (const float*)d_in[0];
    const int*   ei = (const int*)d_in[1];
    const float* W1 = (const float*)d_in[2];
    const float* b1 = (const float*)d_in[3];
    const float* W2 = (const float*)d_in[4];
    const float* b2 = (const float*)d_in[5];
    const float* Wc = (const float*)d_in[6];
    const float* bc = (const float*)d_in[7];
    float* out = (float*)d_out;

    const int n = NNODES;
    const int e = in_sizes[1] / 2;
    const int* src = ei;
    const int* dst = ei + e;

    float *G, *G2, *H, *DINV;
    int *DEG, *ROWPTR, *CSR, *BSUMS;
    cudaGetSymbolAddress((void**)&G,      g_bufG);
    cudaGetSymbolAddress((void**)&G2,     g_bufG2);
    cudaGetSymbolAddress((void**)&H,      g_bufH);
    cudaGetSymbolAddress((void**)&DINV,   g_dinv);
    cudaGetSymbolAddress((void**)&DEG,    g_deg);
    cudaGetSymbolAddress((void**)&ROWPTR, g_rowptr);
    cudaGetSymbolAddress((void**)&CSR,    g_csr_src);
    cudaGetSymbolAddress((void**)&BSUMS,  g_blockSums);

    // side stream + events (host handles, created once)
    static cudaStream_t s_side = nullptr;
    static cudaEvent_t ev_fork = nullptr, ev_pre = nullptr, ev_a0 = nullptr, ev_a1 = nullptr;
    if (!s_side) {
        cudaStreamCreate(&s_side);
        cudaEventCreateWithFlags(&ev_fork, cudaEventDisableTiming);
        cudaEventCreateWithFlags(&ev_pre,  cudaEventDisableTiming);
        cudaEventCreateWithFlags(&ev_a0,   cudaEventDisableTiming);
        cudaEventCreateWithFlags(&ev_a1,   cudaEventDisableTiming);
    }

    const int c0 = CHUNK0;                       // chunk split (multiple of 128)
    const int gemmB_full = (n + 127) / 128;
    const int gemmB_c0   = c0 / 128;
    const int gemmB_c1   = (n - c0 + 127) / 128;
    const int aggB_full  = (int)(((long long)n * 32 + 255) / 256);
    const int aggB_c0    = (int)(((long long)c0 * 32 + 255) / 256);
    const int aggB_c1    = (int)(((long long)(n - c0) * 32 + 255) / 256);
    const int scanB      = (n + 2047) / 2048;

    // ---- fork: CSR build on side stream, GEMM1 on main stream ----
    cudaEventRecord(ev_fork, 0);
    cudaStreamWaitEvent(s_side, ev_fork, 0);

    deg_kernel<<<(e + 255) / 256, 256, 0, s_side>>>(dst, DEG, e);
    scan_block_sums<<<scanB, 256, 0, s_side>>>(DEG, BSUMS, n);
    scan_offsets<<<1, 32, 0, s_side>>>(BSUMS, scanB);
    scan_final<<<scanB, 256, 0, s_side>>>(DEG, BSUMS, ROWPTR, DINV, n);
    scatter_kernel<<<(e + 255) / 256, 256, 0, s_side>>>(src, dst, ROWPTR, DEG, CSR, e);
    cudaEventRecord(ev_pre, s_side);

    gemm_kernel<IN_F><<<gemmB_full, 256>>>(x, W1, G, 0, n);   // independent of CSR/dinv

    // ---- join preprocessing, then pipelined agg1 / GEMM2 ----
    cudaStreamWaitEvent(0, ev_pre, 0);

    // agg1 chunk 0 on main (reads G, writes H[0,c0))
    agg_fused_kernel<true, false><<<aggB_c0, 256>>>((const float4*)G, CSR, ROWPTR, DINV,
                                                    (const float4*)b1, (float4*)H,
                                                    nullptr, nullptr, nullptr, 0, c0);
    cudaEventRecord(ev_a0, 0);

    // agg1 chunk 1 on side (reads G, writes H[c0,n)) — concurrent with GEMM2 chunk 0
    cudaStreamWaitEvent(s_side, ev_a0, 0);
    agg_fused_kernel<true, false><<<aggB_c1, 256, 0, s_side>>>((const float4*)G, CSR, ROWPTR, DINV,
                                                               (const float4*)b1, (float4*)H,
                                                               nullptr, nullptr, nullptr, c0, n);
    cudaEventRecord(ev_a1, s_side);

    // GEMM2 chunk 0 on main: reads H[0,c0), writes G2[0,c0) — disjoint from concurrent agg1(C1)
    gemm_kernel<HID><<<gemmB_c0, 256>>>(H, W2, G2, 0, c0);

    // GEMM2 chunk 1 after agg1(C1) completes
    cudaStreamWaitEvent(0, ev_a1, 0);
    gemm_kernel<HID><<<gemmB_c1, 256>>>(H, W2, G2, c0, n);

    // ---- layer 2 aggregation + fused classifier (reads full G2) ----
    agg_fused_kernel<false, true><<<aggB_full, 256>>>((const float4*)G2, CSR, ROWPTR, DINV,
                                                      (const float4*)b2, nullptr,
                                                      (const float4*)Wc, bc, (float2*)out, 0, n);
}

// round 11
// speedup vs baseline: 1.1839x; 1.0931x over previous
#include <cuda_runtime.h>
#include <cuda_fp16.h>
#include <cstdint>

#define NNODES 100000
#define EDGES  1600000
#define IN_F   165
#define HID    128
#define CHUNK0 50048   // 391 * 128

// Scratch (allocation-free rule: __device__ globals)
__device__ float g_bufG[(size_t)NNODES * HID];   // layer-1 GEMM out: x@W1 (unscaled)
__device__ float g_bufG2[(size_t)NNODES * HID];  // layer-2 GEMM out: H@W2 (unscaled)
__device__ float g_bufH[(size_t)NNODES * HID];   // layer-1 activation, pre-scaled by dinv
__device__ int   g_deg[NNODES];                  // self-restoring: scatter counts it back to 0
__device__ float g_dinv[NNODES];
__device__ int   g_rowptr[NNODES + 1];
__device__ int   g_csr_src[EDGES];
__device__ int   g_blockSums[128];

// ---------------- degree ----------------

__global__ void deg_kernel(const int* __restrict__ dst, int* __restrict__ deg, int e) {
    int i = blockIdx.x * blockDim.x + threadIdx.x;
    if (i < e) atomicAdd(&deg[dst[i]], 1);
}

// ---------------- exclusive prefix scan of deg -> rowptr; also dinv ----------------

__global__ __launch_bounds__(256)
void scan_block_sums(const int* __restrict__ deg, int* __restrict__ blockSums, int n) {
    __shared__ int sdata[256];
    int base = blockIdx.x * 2048;
    int tid = threadIdx.x;
    int s = 0;
#pragma unroll
    for (int j = 0; j < 8; j++) {
        int i = base + tid * 8 + j;
        if (i < n) s += deg[i];
    }
    sdata[tid] = s;
    __syncthreads();
    for (int off = 128; off; off >>= 1) {
        if (tid < off) sdata[tid] += sdata[tid + off];
        __syncthreads();
    }
    if (tid == 0) blockSums[blockIdx.x] = sdata[0];
}

__global__ void scan_offsets(int* __restrict__ blockSums, int nb) {
    int lane = threadIdx.x;            // 32 threads
    int v0 = (lane      < nb) ? blockSums[lane]      : 0;
    int v1 = (lane + 32 < nb) ? blockSums[lane + 32] : 0;
    int s0 = v0;
#pragma unroll
    for (int off = 1; off < 32; off <<= 1) {
        int t = __shfl_up_sync(0xFFFFFFFFu, s0, off);
        if (lane >= off) s0 += t;
    }
    int total0 = __shfl_sync(0xFFFFFFFFu, s0, 31);
    int s1 = v1;
#pragma unroll
    for (int off = 1; off < 32; off <<= 1) {
        int t = __shfl_up_sync(0xFFFFFFFFu, s1, off);
        if (lane >= off) s1 += t;
    }
    if (lane      < nb) blockSums[lane]      = s0 - v0;            // exclusive
    if (lane + 32 < nb) blockSums[lane + 32] = total0 + s1 - v1;
}

__global__ __launch_bounds__(256)
void scan_final(const int* __restrict__ deg, const int* __restrict__ blockSums,
                int* __restrict__ rowptr, float* __restrict__ dinv, int n) {
    __shared__ int tsum[256];
    int base = blockIdx.x * 2048;
    int tid = threadIdx.x;
    int loc[8];
    int dv[8];
    int s = 0;
#pragma unroll
    for (int j = 0; j < 8; j++) {
        int i = base + tid * 8 + j;
        int v = (i < n) ? deg[i] : 0;
        dv[j]  = v;
        loc[j] = s;
        s += v;
    }
    tsum[tid] = s;
    __syncthreads();
    for (int off = 1; off < 256; off <<= 1) {
        int t = (tid >= off) ? tsum[tid - off] : 0;
        __syncthreads();
        tsum[tid] += t;
        __syncthreads();
    }
    int threadOff = tsum[tid] - s;  // exclusive within block
    int cOff = blockSums[blockIdx.x];
#pragma unroll
    for (int j = 0; j < 8; j++) {
        int i = base + tid * 8 + j;
        if (i < n) {
            int rp = cOff + threadOff + loc[j];
            rowptr[i] = rp;
            dinv[i]   = rsqrtf((float)(dv[j] + 1));   // +1 self-loop
            if (i == n - 1) rowptr[n] = rp + dv[j];
        }
    }
}

// ---------------- scatter edges into CSR slots (counts deg back down to 0) ----------

__global__ void scatter_kernel(const int* __restrict__ src, const int* __restrict__ dst,
                               const int* __restrict__ rowptr, int* __restrict__ deg,
                               int* __restrict__ csr, int e) {
    int i = blockIdx.x * blockDim.x + threadIdx.x;
    if (i < e) {
        int d = dst[i];
        int pos = rowptr[d] + atomicAdd(&deg[d], -1) - 1;   // unique slot; deg ends at 0
        csr[pos] = src[i];
    }
}

// ---------------- fp16 split helpers ----------------

__device__ __forceinline__ void split_h(float v, __half& hi, __half& lo) {
    __half h = __float2half_rn(v);
    hi = h;
    lo = __float2half_rn(v - __half2float(h));
}

__device__ __forceinline__ void mma_f16(float* d, uint32_t a0, uint32_t a1,
                                        uint32_t a2, uint32_t a3,
                                        uint32_t b0, uint32_t b1) {
    asm volatile(
        "mma.sync.aligned.m16n8k16.row.col.f32.f16.f16.f32 "
        "{%0,%1,%2,%3}, {%4,%5,%6,%7}, {%8,%9}, {%0,%1,%2,%3};"
        : "+f"(d[0]), "+f"(d[1]), "+f"(d[2]), "+f"(d[3])
        : "r"(a0), "r"(a1), "r"(a2), "r"(a3), "r"(b0), "r"(b1));
}

// ---------------- GEMM (fp16 HMMA, 2-split/3-product): -----------------------------
// G[r0..n1,128] = A[r0..n1,K] @ W[K,128]  (fp32-accurate to ~2^-22)
// 128x128 tile, BK=16, 256 threads = 8 warps (2x4), warp tile 64x32 = 4x4 m16n8k16.
// A in smem as [m][k] halfs (hi/lo), B transposed as [n][k] halfs (hi/lo).
// D = Ah*Bh + Al*Bh + Ah*Bl : 48 MMAs / tile / warp.

template <int K>
__global__ __launch_bounds__(256)
void gemm_kernel(const float* __restrict__ A, const float* __restrict__ W,
                 float* __restrict__ G, int row0, int n1) {
    constexpr int BM = 128, BN = 128, BK = 16;
    constexpr int LDK = 20;                      // half row stride (40B, 4B-aligned)
    constexpr int TILES = (K + BK - 1) / BK;

    __shared__ __align__(16) __half Ah[2][BM][LDK];
    __shared__ __align__(16) __half Al[2][BM][LDK];
    __shared__ __align__(16) __half Bh[2][BN][LDK];
    __shared__ __align__(16) __half Bl[2][BN][LDK];

    const int tid  = threadIdx.x;
    const int wid  = tid >> 5;
    const int lane = tid & 31;
    const int g    = lane >> 2;   // group 0..7
    const int tig  = lane & 3;    // thread-in-group 0..3
    const int wm   = wid & 1;     // 0..1 -> 64 rows each
    const int wn   = wid >> 1;    // 0..3 -> 32 cols each
    const int rowBase = row0 + blockIdx.x * BM;

    float acc[4][4][4];
#pragma unroll
    for (int mf = 0; mf < 4; mf++)
#pragma unroll
        for (int nf = 0; nf < 4; nf++)
#pragma unroll
            for (int q = 0; q < 4; q++) acc[mf][nf][q] = 0.f;

    auto loadAB = [&](int t, int buf) {
        const int k0 = t * BK;
        // A tile: 2048 elems, 8/thread; r = l>>4, kk = l&15
#pragma unroll
        for (int j = 0; j < 8; j++) {
            int l  = tid + 256 * j;
            int r  = l >> 4;
            int kk = l & 15;
            int gr = rowBase + r;
            int gk = k0 + kk;
            float v = 0.f;
            if (gr < n1 && gk < K) v = A[(size_t)gr * K + gk];
            __half hi, lo;
            split_h(v, hi, lo);
            Ah[buf][r][kk] = hi;
            Al[buf][r][kk] = lo;
        }
        // W tile: read [kk][nn] coalesced, store transposed [nn][kk]
#pragma unroll
        for (int j = 0; j < 8; j++) {
            int l  = tid + 256 * j;
            int kk = l >> 7;
            int nn = l & 127;
            int gk = k0 + kk;
            float v = (gk < K) ? W[(size_t)gk * BN + nn] : 0.f;
            __half hi, lo;
            split_h(v, hi, lo);
            Bh[buf][nn][kk] = hi;
            Bl[buf][nn][kk] = lo;
        }
    };

    loadAB(0, 0);
    __syncthreads();

    for (int t = 0; t < TILES; t++) {
        const int cur = t & 1;
        if (t + 1 < TILES) loadAB(t + 1, cur ^ 1);

        // B fragments for all 4 nf (hi & lo)
        uint32_t bh[4][2], bl[4][2];
#pragma unroll
        for (int nf = 0; nf < 4; nf++) {
            int c = wn * 32 + nf * 8 + g;
            bh[nf][0] = *(const uint32_t*)&Bh[cur][c][2 * tig];
            bh[nf][1] = *(const uint32_t*)&Bh[cur][c][2 * tig + 8];
            bl[nf][0] = *(const uint32_t*)&Bl[cur][c][2 * tig];
            bl[nf][1] = *(const uint32_t*)&Bl[cur][c][2 * tig + 8];
        }
#pragma unroll
        for (int mf = 0; mf < 4; mf++) {
            int r  = wm * 64 + mf * 16 + g;
            uint32_t ah0 = *(const uint32_t*)&Ah[cur][r][2 * tig];
            uint32_t ah1 = *(const uint32_t*)&Ah[cur][r + 8][2 * tig];
            uint32_t ah2 = *(const uint32_t*)&Ah[cur][r][2 * tig + 8];
            uint32_t ah3 = *(const uint32_t*)&Ah[cur][r + 8][2 * tig + 8];
            uint32_t al0 = *(const uint32_t*)&Al[cur][r][2 * tig];
            uint32_t al1 = *(const uint32_t*)&Al[cur][r + 8][2 * tig];
            uint32_t al2 = *(const uint32_t*)&Al[cur][r][2 * tig + 8];
            uint32_t al3 = *(const uint32_t*)&Al[cur][r + 8][2 * tig + 8];
#pragma unroll
            for (int nf = 0; nf < 4; nf++) {
                mma_f16(acc[mf][nf], ah0, ah1, ah2, ah3, bh[nf][0], bh[nf][1]);
                mma_f16(acc[mf][nf], al0, al1, al2, al3, bh[nf][0], bh[nf][1]);
                mma_f16(acc[mf][nf], ah0, ah1, ah2, ah3, bl[nf][0], bl[nf][1]);
            }
        }
        __syncthreads();
    }

    // epilogue: d0,d1 -> (r, c), (r, c+1); d2,d3 -> (r+8, c), (r+8, c+1)
#pragma unroll
    for (int mf = 0; mf < 4; mf++) {
        int r0 = rowBase + wm * 64 + mf * 16 + g;
        int r1 = r0 + 8;
#pragma unroll
        for (int nf = 0; nf < 4; nf++) {
            int c = wn * 32 + nf * 8 + 2 * tig;
            if (r0 < n1)
                *(float2*)&G[(size_t)r0 * BN + c] = make_float2(acc[mf][nf][0], acc[mf][nf][1]);
            if (r1 < n1)
                *(float2*)&G[(size_t)r1 * BN + c] = make_float2(acc[mf][nf][2], acc[mf][nf][3]);
        }
    }
}

// ---------------- fused aggregation: warp per node in [n0,n1), CSR, no atomics --------
// EDGE_SCALE=true  (layer 1): acc = dinv[i]*g[i] + Σ dinv[s]*g[s];
//                             h' = dinv[i] * relu(dinv[i]*acc + b)   [pre-scaled for layer 2]
// EDGE_SCALE=false (layer 2): acc = g[i] + Σ g[s]; h = relu(dinv[i]*acc + b)
// FINAL=true: classifier out = h @ Wc + bc (warp reduce)

template <bool EDGE_SCALE, bool FINAL>
__global__ __launch_bounds__(256)
void agg_fused_kernel(const float4* __restrict__ g, const int* __restrict__ csr,
                      const int* __restrict__ rowptr,
                      const float* __restrict__ dinv, const float4* __restrict__ bias,
                      float4* __restrict__ h,
                      const float4* __restrict__ Wc4, const float* __restrict__ bc,
                      float2* __restrict__ out, int n0, int n1) {
    int node = n0 + ((blockIdx.x * blockDim.x + threadIdx.x) >> 5);
    int lane = threadIdx.x & 31;
    if (node >= n1) return;

    const int start = rowptr[node];
    const int end   = rowptr[node + 1];
    const int cnt   = end - start;
    const float s   = dinv[node];

    float4 a[8];
    {   // self-loop term
        float4 v = g[(size_t)node * 32 + lane];
        if (EDGE_SCALE) { v.x *= s; v.y *= s; v.z *= s; v.w *= s; }
        a[0] = v;
    }
#pragma unroll
    for (int i = 1; i < 8; i++) a[i] = make_float4(0.f, 0.f, 0.f, 0.f);

    int j = 0;
    for (; j + 8 <= cnt; j += 8) {
        int idx[8];
#pragma unroll
        for (int u = 0; u < 8; u++) idx[u] = __ldg(&csr[start + j + u]);
        float dv[8];
        if (EDGE_SCALE) {
#pragma unroll
            for (int u = 0; u < 8; u++) dv[u] = __ldg(&dinv[idx[u]]);
        }
#pragma unroll
        for (int u = 0; u < 8; u++) {
            float4 v = g[(size_t)idx[u] * 32 + lane];
            if (EDGE_SCALE) {
                a[u].x = fmaf(dv[u], v.x, a[u].x);
                a[u].y = fmaf(dv[u], v.y, a[u].y);
                a[u].z = fmaf(dv[u], v.z, a[u].z);
                a[u].w = fmaf(dv[u], v.w, a[u].w);
            } else {
                a[u].x += v.x; a[u].y += v.y; a[u].z += v.z; a[u].w += v.w;
            }
        }
    }
    if (j + 4 <= cnt) {
        int idx[4];
#pragma unroll
        for (int u = 0; u < 4; u++) idx[u] = __ldg(&csr[start + j + u]);
        float dv[4];
        if (EDGE_SCALE) {
#pragma unroll
            for (int u = 0; u < 4; u++) dv[u] = __ldg(&dinv[idx[u]]);
        }
#pragma unroll
        for (int u = 0; u < 4; u++) {
            float4 v = g[(size_t)idx[u] * 32 + lane];
            if (EDGE_SCALE) {
                a[u].x = fmaf(dv[u], v.x, a[u].x);
                a[u].y = fmaf(dv[u], v.y, a[u].y);
                a[u].z = fmaf(dv[u], v.z, a[u].z);
                a[u].w = fmaf(dv[u], v.w, a[u].w);
            } else {
                a[u].x += v.x; a[u].y += v.y; a[u].z += v.z; a[u].w += v.w;
            }
        }
        j += 4;
    }
    for (; j < cnt; j++) {
        int s0 = __ldg(&csr[start + j]);
        float4 v = g[(size_t)s0 * 32 + lane];
        if (EDGE_SCALE) {
            float d0 = __ldg(&dinv[s0]);
            a[0].x = fmaf(d0, v.x, a[0].x);
            a[0].y = fmaf(d0, v.y, a[0].y);
            a[0].z = fmaf(d0, v.z, a[0].z);
            a[0].w = fmaf(d0, v.w, a[0].w);
        } else {
            a[0].x += v.x; a[0].y += v.y; a[0].z += v.z; a[0].w += v.w;
        }
    }

    float4 acc;
    acc.x = ((a[0].x + a[1].x) + (a[2].x + a[3].x)) + ((a[4].x + a[5].x) + (a[6].x + a[7].x));
    acc.y = ((a[0].y + a[1].y) + (a[2].y + a[3].y)) + ((a[4].y + a[5].y) + (a[6].y + a[7].y));
    acc.z = ((a[0].z + a[1].z) + (a[2].z + a[3].z)) + ((a[4].z + a[5].z) + (a[6].z + a[7].z));
    acc.w = ((a[0].w + a[1].w) + (a[2].w + a[3].w)) + ((a[4].w + a[5].w) + (a[6].w + a[7].w));

    float4 bv = bias[lane];
    float4 hv;
    hv.x = fmaxf(fmaf(s, acc.x, bv.x), 0.f);
    hv.y = fmaxf(fmaf(s, acc.y, bv.y), 0.f);
    hv.z = fmaxf(fmaf(s, acc.z, bv.z), 0.f);
    hv.w = fmaxf(fmaf(s, acc.w, bv.w), 0.f);

    if (!FINAL) {
        if (EDGE_SCALE) {   // pre-scale for next layer's source role
            hv.x *= s; hv.y *= s; hv.z *= s; hv.w *= s;
        }
        h[(size_t)node * 32 + lane] = hv;
    } else {
        float4 w0 = __ldg(&Wc4[lane * 2]);
        float4 w1 = __ldg(&Wc4[lane * 2 + 1]);
        float p0 = hv.x * w0.x + hv.y * w0.z + hv.z * w1.x + hv.w * w1.z;
        float p1 = hv.x * w0.y + hv.y * w0.w + hv.z * w1.y + hv.w * w1.w;
#pragma unroll
        for (int off = 16; off; off >>= 1) {
            p0 += __shfl_xor_sync(0xFFFFFFFFu, p0, off);
            p1 += __shfl_xor_sync(0xFFFFFFFFu, p1, off);
        }
        if (lane == 0) out[node] = make_float2(p0 + bc[0], p1 + bc[1]);
    }
}

// ---------------- launch ----------------

extern "C" void kernel_launch(void* const* d_in, const int* in_sizes, int n_in,
                              void* d_out, int out_size) {
    const float* x  = (const float*)d_in[0];
    const int*   ei = (const int*)d_in[1];
    const float* W1 = (const float*)d_in[2];
    const float* b1 = (const float*)d_in[3];
    const float* W2 = (const float*)d_in[4];
    const float* b2 = (const float*)d_in[5];
    const float* Wc = (const float*)d_in[6];
    const float* bc = (const float*)d_in[7];
    float* out = (float*)d_out;

    const int n = NNODES;
    const int e = in_sizes[1] / 2;
    const int* src = ei;
    const int* dst = ei + e;

    float *G, *G2, *H, *DINV;
    int *DEG, *ROWPTR, *CSR, *BSUMS;
    cudaGetSymbolAddress((void**)&G,      g_bufG);
    cudaGetSymbolAddress((void**)&G2,     g_bufG2);
    cudaGetSymbolAddress((void**)&H,      g_bufH);
    cudaGetSymbolAddress((void**)&DINV,   g_dinv);
    cudaGetSymbolAddress((void**)&DEG,    g_deg);
    cudaGetSymbolAddress((void**)&ROWPTR, g_rowptr);
    cudaGetSymbolAddress((void**)&CSR,    g_csr_src);
    cudaGetSymbolAddress((void**)&BSUMS,  g_blockSums);

    // side stream + events (host handles, created once)
    static cudaStream_t s_side = nullptr;
    static cudaEvent_t ev_fork = nullptr, ev_pre = nullptr, ev_a0 = nullptr, ev_a1 = nullptr;
    if (!s_side) {
        cudaStreamCreate(&s_side);
        cudaEventCreateWithFlags(&ev_fork, cudaEventDisableTiming);
        cudaEventCreateWithFlags(&ev_pre,  cudaEventDisableTiming);
        cudaEventCreateWithFlags(&ev_a0,   cudaEventDisableTiming);
        cudaEventCreateWithFlags(&ev_a1,   cudaEventDisableTiming);
    }

    const int c0 = CHUNK0;                       // chunk split (multiple of 128)
    const int gemmB_full = (n + 127) / 128;
    const int gemmB_c0   = c0 / 128;
    const int gemmB_c1   = (n - c0 + 127) / 128;
    const int aggB_full  = (int)(((long long)n * 32 + 255) / 256);
    const int aggB_c0    = (int)(((long long)c0 * 32 + 255) / 256);
    const int aggB_c1    = (int)(((long long)(n - c0) * 32 + 255) / 256);
    const int scanB      = (n + 2047) / 2048;

    // ---- fork: CSR build on side stream, GEMM1 on main stream ----
    cudaEventRecord(ev_fork, 0);
    cudaStreamWaitEvent(s_side, ev_fork, 0);

    deg_kernel<<<(e + 255) / 256, 256, 0, s_side>>>(dst, DEG, e);
    scan_block_sums<<<scanB, 256, 0, s_side>>>(DEG, BSUMS, n);
    scan_offsets<<<1, 32, 0, s_side>>>(BSUMS, scanB);
    scan_final<<<scanB, 256, 0, s_side>>>(DEG, BSUMS, ROWPTR, DINV, n);
    scatter_kernel<<<(e + 255) / 256, 256, 0, s_side>>>(src, dst, ROWPTR, DEG, CSR, e);
    cudaEventRecord(ev_pre, s_side);

    gemm_kernel<IN_F><<<gemmB_full, 256>>>(x, W1, G, 0, n);   // independent of CSR/dinv

    // ---- join preprocessing, then pipelined agg1 / GEMM2 ----
    cudaStreamWaitEvent(0, ev_pre, 0);

    // agg1 chunk 0 on main (reads G, writes H[0,c0))
    agg_fused_kernel<true, false><<<aggB_c0, 256>>>((const float4*)G, CSR, ROWPTR, DINV,
                                                    (const float4*)b1, (float4*)H,
                                                    nullptr, nullptr, nullptr, 0, c0);
    cudaEventRecord(ev_a0, 0);

    // agg1 chunk 1 on side (reads G, writes H[c0,n)) — concurrent with GEMM2 chunk 0
    cudaStreamWaitEvent(s_side, ev_a0, 0);
    agg_fused_kernel<true, false><<<aggB_c1, 256, 0, s_side>>>((const float4*)G, CSR, ROWPTR, DINV,
                                                               (const float4*)b1, (float4*)H,
                                                               nullptr, nullptr, nullptr, c0, n);
    cudaEventRecord(ev_a1, s_side);

    // GEMM2 chunk 0 on main: reads H[0,c0), writes G2[0,c0) — disjoint from concurrent agg1(C1)
    gemm_kernel<HID><<<gemmB_c0, 256>>>(H, W2, G2, 0, c0);

    // GEMM2 chunk 1 after agg1(C1) completes
    cudaStreamWaitEvent(0, ev_a1, 0);
    gemm_kernel<HID><<<gemmB_c1, 256>>>(H, W2, G2, c0, n);

    // ---- layer 2 aggregation + fused classifier (reads full G2) ----
    agg_fused_kernel<false, true><<<aggB_full, 256>>>((const float4*)G2, CSR, ROWPTR, DINV,
                                                      (const float4*)b2, nullptr,
                                                      (const float4*)Wc, bc, (float2*)out, 0, n);
}

// round 12
// speedup vs baseline: 1.1970x; 1.0110x over previous
#include <cuda_runtime.h>
#include <cuda_fp16.h>
#include <cstdint>

#define NNODES 100000
#define EDGES  1600000
#define IN_F   165
#define HID    128
#define CHUNK0 50048   // 391 * 128

// Scratch (allocation-free rule: __device__ globals)
__device__ float    g_bufG[(size_t)NNODES * HID];   // layer-1 GEMM out: x@W1 (unscaled)
__device__ float    g_bufG2[(size_t)NNODES * HID];  // layer-2 GEMM out: H@W2 (unscaled)
__device__ uint32_t g_Hh2[(size_t)NNODES * 64];     // H split hi, packed half2 (k-pairs)
__device__ uint32_t g_Hl2[(size_t)NNODES * 64];     // H split lo
__device__ uint32_t g_W1h2[IN_F * 64], g_W1l2[IN_F * 64];   // W1 pre-split (n-pairs)
__device__ uint32_t g_W2h2[HID * 64],  g_W2l2[HID * 64];    // W2 pre-split
__device__ int      g_deg[NNODES];                  // self-restoring
__device__ float    g_dinv[NNODES];
__device__ int      g_rowptr[NNODES + 1];
__device__ int      g_csr_src[EDGES];
__device__ int      g_blockSums[128];

// ---------------- fp16 split helpers ----------------

__device__ __forceinline__ void split_h(float v, __half& hi, __half& lo) {
    __half h = __float2half_rn(v);
    hi = h;
    lo = __float2half_rn(v - __half2float(h));
}

__device__ __forceinline__ uint32_t pack_h2(__half a, __half b) {
    __half2 t = __halves2half2(a, b);
    return *(uint32_t*)&t;
}

__device__ __forceinline__ void mma_f16(float* d, uint32_t a0, uint32_t a1,
                                        uint32_t a2, uint32_t a3,
                                        uint32_t b0, uint32_t b1) {
    asm volatile(
        "mma.sync.aligned.m16n8k16.row.col.f32.f16.f16.f32 "
        "{%0,%1,%2,%3}, {%4,%5,%6,%7}, {%8,%9}, {%0,%1,%2,%3};"
        : "+f"(d[0]), "+f"(d[1]), "+f"(d[2]), "+f"(d[3])
        : "r"(a0), "r"(a1), "r"(a2), "r"(a3), "r"(b0), "r"(b1));
}

// ---------------- W pre-split: float [K][128] -> packed half2 hi/lo [K][64] --------

__global__ void presplit_kernel(const float* __restrict__ W,
                                uint32_t* __restrict__ Wh2, uint32_t* __restrict__ Wl2,
                                int n2) {
    int i = blockIdx.x * blockDim.x + threadIdx.x;
    if (i < n2) {
        float a = W[2 * i], b = W[2 * i + 1];
        __half ah, al, bh, bl;
        split_h(a, ah, al);
        split_h(b, bh, bl);
        Wh2[i] = pack_h2(ah, bh);
        Wl2[i] = pack_h2(al, bl);
    }
}

// ---------------- degree ----------------

__global__ void deg_kernel(const int* __restrict__ dst, int* __restrict__ deg, int e) {
    int i = blockIdx.x * blockDim.x + threadIdx.x;
    if (i < e) atomicAdd(&deg[dst[i]], 1);
}

// ---------------- exclusive prefix scan of deg -> rowptr; also dinv ----------------

__global__ __launch_bounds__(256)
void scan_block_sums(const int* __restrict__ deg, int* __restrict__ blockSums, int n) {
    __shared__ int sdata[256];
    int base = blockIdx.x * 2048;
    int tid = threadIdx.x;
    int s = 0;
#pragma unroll
    for (int j = 0; j < 8; j++) {
        int i = base + tid * 8 + j;
        if (i < n) s += deg[i];
    }
    sdata[tid] = s;
    __syncthreads();
    for (int off = 128; off; off >>= 1) {
        if (tid < off) sdata[tid] += sdata[tid + off];
        __syncthreads();
    }
    if (tid == 0) blockSums[blockIdx.x] = sdata[0];
}

__global__ void scan_offsets(int* __restrict__ blockSums, int nb) {
    int lane = threadIdx.x;            // 32 threads
    int v0 = (lane      < nb) ? blockSums[lane]      : 0;
    int v1 = (lane + 32 < nb) ? blockSums[lane + 32] : 0;
    int s0 = v0;
#pragma unroll
    for (int off = 1; off < 32; off <<= 1) {
        int t = __shfl_up_sync(0xFFFFFFFFu, s0, off);
        if (lane >= off) s0 += t;
    }
    int total0 = __shfl_sync(0xFFFFFFFFu, s0, 31);
    int s1 = v1;
#pragma unroll
    for (int off = 1; off < 32; off <<= 1) {
        int t = __shfl_up_sync(0xFFFFFFFFu, s1, off);
        if (lane >= off) s1 += t;
    }
    if (lane      < nb) blockSums[lane]      = s0 - v0;            // exclusive
    if (lane + 32 < nb) blockSums[lane + 32] = total0 + s1 - v1;
}

__global__ __launch_bounds__(256)
void scan_final(const int* __restrict__ deg, const int* __restrict__ blockSums,
                int* __restrict__ rowptr, float* __restrict__ dinv, int n) {
    __shared__ int tsum[256];
    int base = blockIdx.x * 2048;
    int tid = threadIdx.x;
    int loc[8];
    int dv[8];
    int s = 0;
#pragma unroll
    for (int j = 0; j < 8; j++) {
        int i = base + tid * 8 + j;
        int v = (i < n) ? deg[i] : 0;
        dv[j]  = v;
        loc[j] = s;
        s += v;
    }
    tsum[tid] = s;
    __syncthreads();
    for (int off = 1; off < 256; off <<= 1) {
        int t = (tid >= off) ? tsum[tid - off] : 0;
        __syncthreads();
        tsum[tid] += t;
        __syncthreads();
    }
    int threadOff = tsum[tid] - s;  // exclusive within block
    int cOff = blockSums[blockIdx.x];
#pragma unroll
    for (int j = 0; j < 8; j++) {
        int i = base + tid * 8 + j;
        if (i < n) {
            int rp = cOff + threadOff + loc[j];
            rowptr[i] = rp;
            dinv[i]   = rsqrtf((float)(dv[j] + 1));   // +1 self-loop
            if (i == n - 1) rowptr[n] = rp + dv[j];
        }
    }
}

// ---------------- scatter edges into CSR slots (counts deg back down to 0) ----------

__global__ void scatter_kernel(const int* __restrict__ src, const int* __restrict__ dst,
                               const int* __restrict__ rowptr, int* __restrict__ deg,
                               int* __restrict__ csr, int e) {
    int i = blockIdx.x * blockDim.x + threadIdx.x;
    if (i < e) {
        int d = dst[i];
        int pos = rowptr[d] + atomicAdd(&deg[d], -1) - 1;   // unique slot; deg ends at 0
        csr[pos] = src[i];
    }
}

// ---------------- GEMM (fp16 HMMA, 2-split/3-product, pre-split operands): ---------
// G[r0..n1,128] = A[r0..n1,K] @ W[K,128]  (fp32-accurate to ~2^-22)
// 128x128 tile, BK=16, 256 threads = 8 warps (2x4), warp tile 64x32 = 4x4 m16n8k16.
// PRE=true : A supplied pre-split as packed half2 hi/lo (k-pairs)  [GEMM2: H]
// PRE=false: A is float, split in-kernel                           [GEMM1: x]
// B (W) always pre-split in global memory (n-pairs).

template <int K, bool PRE>
__global__ __launch_bounds__(256)
void gemm_kernel(const float* __restrict__ A,
                 const uint32_t* __restrict__ Ah2, const uint32_t* __restrict__ Al2,
                 const uint32_t* __restrict__ Wh2, const uint32_t* __restrict__ Wl2,
                 float* __restrict__ G, int row0, int n1) {
    constexpr int BM = 128, BN = 128, BK = 16;
    constexpr int LDK = 20;                      // half row stride (40B)
    constexpr int TILES = (K + BK - 1) / BK;

    __shared__ __align__(16) __half Ah[2][BM][LDK];
    __shared__ __align__(16) __half Al[2][BM][LDK];
    __shared__ __align__(16) __half Bh[2][BN][LDK];
    __shared__ __align__(16) __half Bl[2][BN][LDK];

    const int tid  = threadIdx.x;
    const int wid  = tid >> 5;
    const int lane = tid & 31;
    const int g    = lane >> 2;   // group 0..7
    const int tig  = lane & 3;    // thread-in-group 0..3
    const int wm   = wid & 1;     // 0..1 -> 64 rows each
    const int wn   = wid >> 1;    // 0..3 -> 32 cols each
    const int rowBase = row0 + blockIdx.x * BM;

    float acc[4][4][4];
#pragma unroll
    for (int mf = 0; mf < 4; mf++)
#pragma unroll
        for (int nf = 0; nf < 4; nf++)
#pragma unroll
            for (int q = 0; q < 4; q++) acc[mf][nf][q] = 0.f;

    auto loadAB = [&](int t, int buf) {
        const int k0 = t * BK;
        // ---- A tile: 1024 k-pairs, 4 per thread ----
        if (PRE) {
#pragma unroll
            for (int j = 0; j < 4; j++) {
                int q = tid + 256 * j;
                int r = q >> 3, kp = q & 7;
                int gr = rowBase + r;
                uint32_t vh = 0, vl = 0;
                if (gr < n1) {
                    size_t idx = (size_t)gr * 64 + (k0 >> 1) + kp;
                    vh = Ah2[idx];
                    vl = Al2[idx];
                }
                *(uint32_t*)&Ah[buf][r][2 * kp] = vh;
                *(uint32_t*)&Al[buf][r][2 * kp] = vl;
            }
        } else {
#pragma unroll
            for (int j = 0; j < 4; j++) {
                int q = tid + 256 * j;
                int r = q >> 3, kp = q & 7;
                int gr = rowBase + r;
                int gk = k0 + 2 * kp;
                float v0 = 0.f, v1 = 0.f;
                if (gr < n1) {
                    if (gk     < K) v0 = A[(size_t)gr * K + gk];
                    if (gk + 1 < K) v1 = A[(size_t)gr * K + gk + 1];
                }
                __half h0, l0, h1, l1;
                split_h(v0, h0, l0);
                split_h(v1, h1, l1);
                *(uint32_t*)&Ah[buf][r][2 * kp] = pack_h2(h0, h1);
                *(uint32_t*)&Al[buf][r][2 * kp] = pack_h2(l0, l1);
            }
        }
        // ---- B tile from pre-split W: 1024 n-pairs, 4 per thread (transposed store) --
#pragma unroll
        for (int j = 0; j < 4; j++) {
            int l  = tid + 256 * j;
            int kk = l >> 6, np = l & 63;
            int gk = k0 + kk;
            uint32_t vh = 0, vl = 0;
            if (gk < K) {
                vh = Wh2[gk * 64 + np];
                vl = Wl2[gk * 64 + np];
            }
            __half2 h2 = *(__half2*)&vh;
            __half2 l2 = *(__half2*)&vl;
            Bh[buf][2 * np][kk]     = __low2half(h2);
            Bh[buf][2 * np + 1][kk] = __high2half(h2);
            Bl[buf][2 * np][kk]     = __low2half(l2);
            Bl[buf][2 * np + 1][kk] = __high2half(l2);
        }
    };

    loadAB(0, 0);
    __syncthreads();

    for (int t = 0; t < TILES; t++) {
        const int cur = t & 1;
        if (t + 1 < TILES) loadAB(t + 1, cur ^ 1);

        // B fragments for all 4 nf (hi & lo)
        uint32_t bh[4][2], bl[4][2];
#pragma unroll
        for (int nf = 0; nf < 4; nf++) {
            int c = wn * 32 + nf * 8 + g;
            bh[nf][0] = *(const uint32_t*)&Bh[cur][c][2 * tig];
            bh[nf][1] = *(const uint32_t*)&Bh[cur][c][2 * tig + 8];
            bl[nf][0] = *(const uint32_t*)&Bl[cur][c][2 * tig];
            bl[nf][1] = *(const uint32_t*)&Bl[cur][c][2 * tig + 8];
        }
#pragma unroll
        for (int mf = 0; mf < 4; mf++) {
            int r  = wm * 64 + mf * 16 + g;
            uint32_t ah0 = *(const uint32_t*)&Ah[cur][r][2 * tig];
            uint32_t ah1 = *(const uint32_t*)&Ah[cur][r + 8][2 * tig];
            uint32_t ah2 = *(const uint32_t*)&Ah[cur][r][2 * tig + 8];
            uint32_t ah3 = *(const uint32_t*)&Ah[cur][r + 8][2 * tig + 8];
            uint32_t al0 = *(const uint32_t*)&Al[cur][r][2 * tig];
            uint32_t al1 = *(const uint32_t*)&Al[cur][r + 8][2 * tig];
            uint32_t al2 = *(const uint32_t*)&Al[cur][r][2 * tig + 8];
            uint32_t al3 = *(const uint32_t*)&Al[cur][r + 8][2 * tig + 8];
#pragma unroll
            for (int nf = 0; nf < 4; nf++) {
                mma_f16(acc[mf][nf], ah0, ah1, ah2, ah3, bh[nf][0], bh[nf][1]);
                mma_f16(acc[mf][nf], al0, al1, al2, al3, bh[nf][0], bh[nf][1]);
                mma_f16(acc[mf][nf], ah0, ah1, ah2, ah3, bl[nf][0], bl[nf][1]);
            }
        }
        __syncthreads();
    }

    // epilogue
#pragma unroll
    for (int mf = 0; mf < 4; mf++) {
        int r0 = rowBase + wm * 64 + mf * 16 + g;
        int r1 = r0 + 8;
#pragma unroll
        for (int nf = 0; nf < 4; nf++) {
            int c = wn * 32 + nf * 8 + 2 * tig;
            if (r0 < n1)
                *(float2*)&G[(size_t)r0 * BN + c] = make_float2(acc[mf][nf][0], acc[mf][nf][1]);
            if (r1 < n1)
                *(float2*)&G[(size_t)r1 * BN + c] = make_float2(acc[mf][nf][2], acc[mf][nf][3]);
        }
    }
}

// ---------------- fused aggregation: warp per node in [n0,n1), CSR, no atomics --------
// EDGE_SCALE=true  (layer 1): acc = dinv[i]*g[i] + Σ dinv[s]*g[s];
//      h' = dinv[i]*relu(dinv[i]*acc + b), written SPLIT as packed half2 hi/lo
// EDGE_SCALE=false (layer 2): acc = g[i] + Σ g[s]; h = relu(dinv[i]*acc + b)
// FINAL=true: classifier out = h @ Wc + bc (warp reduce)

template <bool EDGE_SCALE, bool FINAL>
__global__ __launch_bounds__(256)
void agg_fused_kernel(const float4* __restrict__ g, const int* __restrict__ csr,
                      const int* __restrict__ rowptr,
                      const float* __restrict__ dinv, const float4* __restrict__ bias,
                      uint2* __restrict__ hh2, uint2* __restrict__ hl2,
                      const float4* __restrict__ Wc4, const float* __restrict__ bc,
                      float2* __restrict__ out, int n0, int n1) {
    int node = n0 + ((blockIdx.x * blockDim.x + threadIdx.x) >> 5);
    int lane = threadIdx.x & 31;
    if (node >= n1) return;

    const int start = rowptr[node];
    const int end   = rowptr[node + 1];
    const int cnt   = end - start;
    const float s   = dinv[node];

    float4 a[8];
    {   // self-loop term
        float4 v = g[(size_t)node * 32 + lane];
        if (EDGE_SCALE) { v.x *= s; v.y *= s; v.z *= s; v.w *= s; }
        a[0] = v;
    }
#pragma unroll
    for (int i = 1; i < 8; i++) a[i] = make_float4(0.f, 0.f, 0.f, 0.f);

    int j = 0;
    for (; j + 8 <= cnt; j += 8) {
        int idx[8];
#pragma unroll
        for (int u = 0; u < 8; u++) idx[u] = __ldg(&csr[start + j + u]);
        float dv[8];
        if (EDGE_SCALE) {
#pragma unroll
            for (int u = 0; u < 8; u++) dv[u] = __ldg(&dinv[idx[u]]);
        }
#pragma unroll
        for (int u = 0; u < 8; u++) {
            float4 v = g[(size_t)idx[u] * 32 + lane];
            if (EDGE_SCALE) {
                a[u].x = fmaf(dv[u], v.x, a[u].x);
                a[u].y = fmaf(dv[u], v.y, a[u].y);
                a[u].z = fmaf(dv[u], v.z, a[u].z);
                a[u].w = fmaf(dv[u], v.w, a[u].w);
            } else {
                a[u].x += v.x; a[u].y += v.y; a[u].z += v.z; a[u].w += v.w;
            }
        }
    }
    if (j + 4 <= cnt) {
        int idx[4];
#pragma unroll
        for (int u = 0; u < 4; u++) idx[u] = __ldg(&csr[start + j + u]);
        float dv[4];
        if (EDGE_SCALE) {
#pragma unroll
            for (int u = 0; u < 4; u++) dv[u] = __ldg(&dinv[idx[u]]);
        }
#pragma unroll
        for (int u = 0; u < 4; u++) {
            float4 v = g[(size_t)idx[u] * 32 + lane];
            if (EDGE_SCALE) {
                a[u].x = fmaf(dv[u], v.x, a[u].x);
                a[u].y = fmaf(dv[u], v.y, a[u].y);
                a[u].z = fmaf(dv[u], v.z, a[u].z);
                a[u].w = fmaf(dv[u], v.w, a[u].w);
            } else {
                a[u].x += v.x; a[u].y += v.y; a[u].z += v.z; a[u].w += v.w;
            }
        }
        j += 4;
    }
    for (; j < cnt; j++) {
        int s0 = __ldg(&csr[start + j]);
        float4 v = g[(size_t)s0 * 32 + lane];
        if (EDGE_SCALE) {
            float d0 = __ldg(&dinv[s0]);
            a[0].x = fmaf(d0, v.x, a[0].x);
            a[0].y = fmaf(d0, v.y, a[0].y);
            a[0].z = fmaf(d0, v.z, a[0].z);
            a[0].w = fmaf(d0, v.w, a[0].w);
        } else {
            a[0].x += v.x; a[0].y += v.y; a[0].z += v.z; a[0].w += v.w;
        }
    }

    float4 acc;
    acc.x = ((a[0].x + a[1].x) + (a[2].x + a[3].x)) + ((a[4].x + a[5].x) + (a[6].x + a[7].x));
    acc.y = ((a[0].y + a[1].y) + (a[2].y + a[3].y)) + ((a[4].y + a[5].y) + (a[6].y + a[7].y));
    acc.z = ((a[0].z + a[1].z) + (a[2].z + a[3].z)) + ((a[4].z + a[5].z) + (a[6].z + a[7].z));
    acc.w = ((a[0].w + a[1].w) + (a[2].w + a[3].w)) + ((a[4].w + a[5].w) + (a[6].w + a[7].w));

    float4 bv = bias[lane];
    float4 hv;
    hv.x = fmaxf(fmaf(s, acc.x, bv.x), 0.f);
    hv.y = fmaxf(fmaf(s, acc.y, bv.y), 0.f);
    hv.z = fmaxf(fmaf(s, acc.z, bv.z), 0.f);
    hv.w = fmaxf(fmaf(s, acc.w, bv.w), 0.f);

    if (!FINAL) {
        if (EDGE_SCALE) {   // pre-scale for next layer's source role
            hv.x *= s; hv.y *= s; hv.z *= s; hv.w *= s;
        }
        // write pre-split halves (hi/lo), packed as k-pairs
        __half hx, lx, hy, ly, hz, lz, hw, lw;
        split_h(hv.x, hx, lx);
        split_h(hv.y, hy, ly);
        split_h(hv.z, hz, lz);
        split_h(hv.w, hw, lw);
        uint2 vh, vl;
        vh.x = pack_h2(hx, hy); vh.y = pack_h2(hz, hw);
        vl.x = pack_h2(lx, ly); vl.y = pack_h2(lz, lw);
        hh2[(size_t)node * 32 + lane] = vh;
        hl2[(size_t)node * 32 + lane] = vl;
    } else {
        float4 w0 = __ldg(&Wc4[lane * 2]);
        float4 w1 = __ldg(&Wc4[lane * 2 + 1]);
        float p0 = hv.x * w0.x + hv.y * w0.z + hv.z * w1.x + hv.w * w1.z;
        float p1 = hv.x * w0.y + hv.y * w0.w + hv.z * w1.y + hv.w * w1.w;
#pragma unroll
        for (int off = 16; off; off >>= 1) {
            p0 += __shfl_xor_sync(0xFFFFFFFFu, p0, off);
            p1 += __shfl_xor_sync(0xFFFFFFFFu, p1, off);
        }
        if (lane == 0) out[node] = make_float2(p0 + bc[0], p1 + bc[1]);
    }
}

// ---------------- launch ----------------

extern "C" void kernel_launch(void* const* d_in, const int* in_sizes, int n_in,
                              void* d_out, int out_size) {
    const float* x  = (const float*)d_in[0];
    const int*   ei = (const int*)d_in[1];
    const float* W1 = (const float*)d_in[2];
    const float* b1 = (const float*)d_in[3];
    const float* W2 = (const float*)d_in[4];
    const float* b2 = (const float*)d_in[5];
    const float* Wc = (const float*)d_in[6];
    const float* bc = (const float*)d_in[7];
    float* out = (float*)d_out;

    const int n = NNODES;
    const int e = in_sizes[1] / 2;
    const int* src = ei;
    const int* dst = ei + e;

    float *G, *G2, *DINV;
    uint32_t *HH2, *HL2, *W1H, *W1L, *W2H, *W2L;
    int *DEG, *ROWPTR, *CSR, *BSUMS;
    cudaGetSymbolAddress((void**)&G,      g_bufG);
    cudaGetSymbolAddress((void**)&G2,     g_bufG2);
    cudaGetSymbolAddress((void**)&HH2,    g_Hh2);
    cudaGetSymbolAddress((void**)&HL2,    g_Hl2);
    cudaGetSymbolAddress((void**)&W1H,    g_W1h2);
    cudaGetSymbolAddress((void**)&W1L,    g_W1l2);
    cudaGetSymbolAddress((void**)&W2H,    g_W2h2);
    cudaGetSymbolAddress((void**)&W2L,    g_W2l2);
    cudaGetSymbolAddress((void**)&DINV,   g_dinv);
    cudaGetSymbolAddress((void**)&DEG,    g_deg);
    cudaGetSymbolAddress((void**)&ROWPTR, g_rowptr);
    cudaGetSymbolAddress((void**)&CSR,    g_csr_src);
    cudaGetSymbolAddress((void**)&BSUMS,  g_blockSums);

    // side stream + events (host handles, created once)
    static cudaStream_t s_side = nullptr;
    static cudaEvent_t ev_fork = nullptr, ev_pre = nullptr, ev_a0 = nullptr, ev_a1 = nullptr;
    if (!s_side) {
        cudaStreamCreate(&s_side);
        cudaEventCreateWithFlags(&ev_fork, cudaEventDisableTiming);
        cudaEventCreateWithFlags(&ev_pre,  cudaEventDisableTiming);
        cudaEventCreateWithFlags(&ev_a0,   cudaEventDisableTiming);
        cudaEventCreateWithFlags(&ev_a1,   cudaEventDisableTiming);
    }

    const int c0 = CHUNK0;                       // chunk split (multiple of 128)
    const int gemmB_full = (n + 127) / 128;
    const int gemmB_c0   = c0 / 128;
    const int gemmB_c1   = (n - c0 + 127) / 128;
    const int aggB_full  = (int)(((long long)n * 32 + 255) / 256);
    const int aggB_c0    = (int)(((long long)c0 * 32 + 255) / 256);
    const int aggB_c1    = (int)(((long long)(n - c0) * 32 + 255) / 256);
    const int scanB      = (n + 2047) / 2048;

    // ---- fork: CSR build + W2 pre-split on side stream; W1 pre-split + GEMM1 on main ----
    cudaEventRecord(ev_fork, 0);
    cudaStreamWaitEvent(s_side, ev_fork, 0);

    presplit_kernel<<<(HID * 64 + 255) / 256, 256, 0, s_side>>>(W2, W2H, W2L, HID * 64);
    deg_kernel<<<(e + 255) / 256, 256, 0, s_side>>>(dst, DEG, e);
    scan_block_sums<<<scanB, 256, 0, s_side>>>(DEG, BSUMS, n);
    scan_offsets<<<1, 32, 0, s_side>>>(BSUMS, scanB);
    scan_final<<<scanB, 256, 0, s_side>>>(DEG, BSUMS, ROWPTR, DINV, n);
    scatter_kernel<<<(e + 255) / 256, 256, 0, s_side>>>(src, dst, ROWPTR, DEG, CSR, e);
    cudaEventRecord(ev_pre, s_side);

    presplit_kernel<<<(IN_F * 64 + 255) / 256, 256>>>(W1, W1H, W1L, IN_F * 64);
    gemm_kernel<IN_F, false><<<gemmB_full, 256>>>(x, nullptr, nullptr, W1H, W1L, G, 0, n);

    // ---- join preprocessing, then pipelined agg1 / GEMM2 ----
    cudaStreamWaitEvent(0, ev_pre, 0);

    // agg1 chunk 0 on main (reads G, writes Hh2/Hl2[0,c0))
    agg_fused_kernel<true, false><<<aggB_c0, 256>>>((const float4*)G, CSR, ROWPTR, DINV,
                                                    (const float4*)b1,
                                                    (uint2*)HH2, (uint2*)HL2,
                                                    nullptr, nullptr, nullptr, 0, c0);
    cudaEventRecord(ev_a0, 0);

    // agg1 chunk 1 on side (reads G, writes Hh2/Hl2[c0,n)) — concurrent with GEMM2 chunk 0
    cudaStreamWaitEvent(s_side, ev_a0, 0);
    agg_fused_kernel<true, false><<<aggB_c1, 256, 0, s_side>>>((const float4*)G, CSR, ROWPTR, DINV,
                                                               (const float4*)b1,
                                                               (uint2*)HH2, (uint2*)HL2,
                                                               nullptr, nullptr, nullptr, c0, n);
    cudaEventRecord(ev_a1, s_side);

    // GEMM2 chunk 0 on main: reads Hh2/Hl2[0,c0), writes G2[0,c0)
    gemm_kernel<HID, true><<<gemmB_c0, 256>>>(nullptr, HH2, HL2, W2H, W2L, G2, 0, c0);

    // GEMM2 chunk 1 after agg1(C1) completes
    cudaStreamWaitEvent(0, ev_a1, 0);
    gemm_kernel<HID, true><<<gemmB_c1, 256>>>(nullptr, HH2, HL2, W2H, W2L, G2, c0, n);

    // ---- layer 2 aggregation + fused classifier (reads full G2) ----
    agg_fused_kernel<false, true><<<aggB_full, 256>>>((const float4*)G2, CSR, ROWPTR, DINV,
                                                      (const float4*)b2,
                                                      nullptr, nullptr,
                                                      (const float4*)Wc, bc, (float2*)out, 0, n);
}

// round 13
// speedup vs baseline: 1.3131x; 1.0971x over previous
#include <cuda_runtime.h>
#include <cuda_fp16.h>
#include <cstdint>

#define NNODES 100000
#define EDGES  1600000
#define IN_F   165
#define HID    128
#define CHUNK0 50048   // 391 * 128

// Scratch (allocation-free rule: __device__ globals)
__device__ uint32_t g_bufG[(size_t)NNODES * 64];    // layer-1 GEMM out, packed half2 (k-pairs)
__device__ uint32_t g_bufG2[(size_t)NNODES * 64];   // layer-2 GEMM out, packed half2
__device__ uint32_t g_Hh2[(size_t)NNODES * 64];     // H split hi, packed half2 (k-pairs)
__device__ uint32_t g_Hl2[(size_t)NNODES * 64];     // H split lo
__device__ uint32_t g_W1h2[IN_F * 64], g_W1l2[IN_F * 64];   // W1 pre-split (n-pairs)
__device__ uint32_t g_W2h2[HID * 64],  g_W2l2[HID * 64];    // W2 pre-split
__device__ int      g_deg[NNODES];                  // self-restoring
__device__ float    g_dinv[NNODES];
__device__ int      g_rowptr[NNODES + 1];
__device__ int      g_csr_src[EDGES];
__device__ int      g_blockSums[128];

// ---------------- fp16 helpers ----------------

__device__ __forceinline__ void split_h(float v, __half& hi, __half& lo) {
    __half h = __float2half_rn(v);
    hi = h;
    lo = __float2half_rn(v - __half2float(h));
}

__device__ __forceinline__ uint32_t pack_h2(__half a, __half b) {
    __half2 t = __halves2half2(a, b);
    return *(uint32_t*)&t;
}

__device__ __forceinline__ uint32_t pack_f2(float a, float b) {
    __half2 t = __floats2half2_rn(a, b);
    return *(uint32_t*)&t;
}

__device__ __forceinline__ float4 unpack_h4(uint2 u) {
    float2 fa = __half22float2(*(__half2*)&u.x);
    float2 fb = __half22float2(*(__half2*)&u.y);
    return make_float4(fa.x, fa.y, fb.x, fb.y);
}

__device__ __forceinline__ void mma_f16(float* d, uint32_t a0, uint32_t a1,
                                        uint32_t a2, uint32_t a3,
                                        uint32_t b0, uint32_t b1) {
    asm volatile(
        "mma.sync.aligned.m16n8k16.row.col.f32.f16.f16.f32 "
        "{%0,%1,%2,%3}, {%4,%5,%6,%7}, {%8,%9}, {%0,%1,%2,%3};"
        : "+f"(d[0]), "+f"(d[1]), "+f"(d[2]), "+f"(d[3])
        : "r"(a0), "r"(a1), "r"(a2), "r"(a3), "r"(b0), "r"(b1));
}

// ---------------- W pre-split: float [K][128] -> packed half2 hi/lo [K][64] --------

__global__ void presplit_kernel(const float* __restrict__ W,
                                uint32_t* __restrict__ Wh2, uint32_t* __restrict__ Wl2,
                                int n2) {
    int i = blockIdx.x * blockDim.x + threadIdx.x;
    if (i < n2) {
        float a = W[2 * i], b = W[2 * i + 1];
        __half ah, al, bh, bl;
        split_h(a, ah, al);
        split_h(b, bh, bl);
        Wh2[i] = pack_h2(ah, bh);
        Wl2[i] = pack_h2(al, bl);
    }
}

// ---------------- degree ----------------

__global__ void deg_kernel(const int* __restrict__ dst, int* __restrict__ deg, int e) {
    int i = blockIdx.x * blockDim.x + threadIdx.x;
    if (i < e) atomicAdd(&deg[dst[i]], 1);
}

// ---------------- exclusive prefix scan of deg -> rowptr; also dinv ----------------

__global__ __launch_bounds__(256)
void scan_block_sums(const int* __restrict__ deg, int* __restrict__ blockSums, int n) {
    __shared__ int sdata[256];
    int base = blockIdx.x * 2048;
    int tid = threadIdx.x;
    int s = 0;
#pragma unroll
    for (int j = 0; j < 8; j++) {
        int i = base + tid * 8 + j;
        if (i < n) s += deg[i];
    }
    sdata[tid] = s;
    __syncthreads();
    for (int off = 128; off; off >>= 1) {
        if (tid < off) sdata[tid] += sdata[tid + off];
        __syncthreads();
    }
    if (tid == 0) blockSums[blockIdx.x] = sdata[0];
}

__global__ void scan_offsets(int* __restrict__ blockSums, int nb) {
    int lane = threadIdx.x;            // 32 threads
    int v0 = (lane      < nb) ? blockSums[lane]      : 0;
    int v1 = (lane + 32 < nb) ? blockSums[lane + 32] : 0;
    int s0 = v0;
#pragma unroll
    for (int off = 1; off < 32; off <<= 1) {
        int t = __shfl_up_sync(0xFFFFFFFFu, s0, off);
        if (lane >= off) s0 += t;
    }
    int total0 = __shfl_sync(0xFFFFFFFFu, s0, 31);
    int s1 = v1;
#pragma unroll
    for (int off = 1; off < 32; off <<= 1) {
        int t = __shfl_up_sync(0xFFFFFFFFu, s1, off);
        if (lane >= off) s1 += t;
    }
    if (lane      < nb) blockSums[lane]      = s0 - v0;            // exclusive
    if (lane + 32 < nb) blockSums[lane + 32] = total0 + s1 - v1;
}

__global__ __launch_bounds__(256)
void scan_final(const int* __restrict__ deg, const int* __restrict__ blockSums,
                int* __restrict__ rowptr, float* __restrict__ dinv, int n) {
    __shared__ int tsum[256];
    int base = blockIdx.x * 2048;
    int tid = threadIdx.x;
    int loc[8];
    int dv[8];
    int s = 0;
#pragma unroll
    for (int j = 0; j < 8; j++) {
        int i = base + tid * 8 + j;
        int v = (i < n) ? deg[i] : 0;
        dv[j]  = v;
        loc[j] = s;
        s += v;
    }
    tsum[tid] = s;
    __syncthreads();
    for (int off = 1; off < 256; off <<= 1) {
        int t = (tid >= off) ? tsum[tid - off] : 0;
        __syncthreads();
        tsum[tid] += t;
        __syncthreads();
    }
    int threadOff = tsum[tid] - s;  // exclusive within block
    int cOff = blockSums[blockIdx.x];
#pragma unroll
    for (int j = 0; j < 8; j++) {
        int i = base + tid * 8 + j;
        if (i < n) {
            int rp = cOff + threadOff + loc[j];
            rowptr[i] = rp;
            dinv[i]   = rsqrtf((float)(dv[j] + 1));   // +1 self-loop
            if (i == n - 1) rowptr[n] = rp + dv[j];
        }
    }
}

// ---------------- scatter edges into CSR slots (counts deg back down to 0) ----------

__global__ void scatter_kernel(const int* __restrict__ src, const int* __restrict__ dst,
                               const int* __restrict__ rowptr, int* __restrict__ deg,
                               int* __restrict__ csr, int e) {
    int i = blockIdx.x * blockDim.x + threadIdx.x;
    if (i < e) {
        int d = dst[i];
        int pos = rowptr[d] + atomicAdd(&deg[d], -1) - 1;   // unique slot; deg ends at 0
        csr[pos] = src[i];
    }
}

// ---------------- GEMM (fp16 HMMA, 2-split/3-product, pre-split operands): ---------
// Gh2[r0..n1, 64] = packed-half2( A[r0..n1,K] @ W[K,128] )
// 128x128 tile, BK=16, 256 threads = 8 warps (2x4), warp tile 64x32 = 4x4 m16n8k16.
// PRE=true : A supplied pre-split as packed half2 hi/lo (k-pairs)  [GEMM2: H]
// PRE=false: A is float, split in-kernel                           [GEMM1: x]

template <int K, bool PRE>
__global__ __launch_bounds__(256)
void gemm_kernel(const float* __restrict__ A,
                 const uint32_t* __restrict__ Ah2, const uint32_t* __restrict__ Al2,
                 const uint32_t* __restrict__ Wh2, const uint32_t* __restrict__ Wl2,
                 uint32_t* __restrict__ Gh2, int row0, int n1) {
    constexpr int BM = 128, BK = 16;
    constexpr int LDK = 20;                      // half row stride (40B)
    constexpr int TILES = (K + BK - 1) / BK;

    __shared__ __align__(16) __half Ah[2][BM][LDK];
    __shared__ __align__(16) __half Al[2][BM][LDK];
    __shared__ __align__(16) __half Bh[2][128][LDK];
    __shared__ __align__(16) __half Bl[2][128][LDK];

    const int tid  = threadIdx.x;
    const int wid  = tid >> 5;
    const int lane = tid & 31;
    const int g    = lane >> 2;   // group 0..7
    const int tig  = lane & 3;    // thread-in-group 0..3
    const int wm   = wid & 1;     // 0..1 -> 64 rows each
    const int wn   = wid >> 1;    // 0..3 -> 32 cols each
    const int rowBase = row0 + blockIdx.x * BM;

    float acc[4][4][4];
#pragma unroll
    for (int mf = 0; mf < 4; mf++)
#pragma unroll
        for (int nf = 0; nf < 4; nf++)
#pragma unroll
            for (int q = 0; q < 4; q++) acc[mf][nf][q] = 0.f;

    auto loadAB = [&](int t, int buf) {
        const int k0 = t * BK;
        // ---- A tile: 1024 k-pairs, 4 per thread ----
        if (PRE) {
#pragma unroll
            for (int j = 0; j < 4; j++) {
                int q = tid + 256 * j;
                int r = q >> 3, kp = q & 7;
                int gr = rowBase + r;
                uint32_t vh = 0, vl = 0;
                if (gr < n1) {
                    size_t idx = (size_t)gr * 64 + (k0 >> 1) + kp;
                    vh = Ah2[idx];
                    vl = Al2[idx];
                }
                *(uint32_t*)&Ah[buf][r][2 * kp] = vh;
                *(uint32_t*)&Al[buf][r][2 * kp] = vl;
            }
        } else {
#pragma unroll
            for (int j = 0; j < 4; j++) {
                int q = tid + 256 * j;
                int r = q >> 3, kp = q & 7;
                int gr = rowBase + r;
                int gk = k0 + 2 * kp;
                float v0 = 0.f, v1 = 0.f;
                if (gr < n1) {
                    if (gk     < K) v0 = A[(size_t)gr * K + gk];
                    if (gk + 1 < K) v1 = A[(size_t)gr * K + gk + 1];
                }
                __half h0, l0, h1, l1;
                split_h(v0, h0, l0);
                split_h(v1, h1, l1);
                *(uint32_t*)&Ah[buf][r][2 * kp] = pack_h2(h0, h1);
                *(uint32_t*)&Al[buf][r][2 * kp] = pack_h2(l0, l1);
            }
        }
        // ---- B tile from pre-split W: 1024 n-pairs, 4 per thread (transposed store) --
#pragma unroll
        for (int j = 0; j < 4; j++) {
            int l  = tid + 256 * j;
            int kk = l >> 6, np = l & 63;
            int gk = k0 + kk;
            uint32_t vh = 0, vl = 0;
            if (gk < K) {
                vh = Wh2[gk * 64 + np];
                vl = Wl2[gk * 64 + np];
            }
            __half2 h2 = *(__half2*)&vh;
            __half2 l2 = *(__half2*)&vl;
            Bh[buf][2 * np][kk]     = __low2half(h2);
            Bh[buf][2 * np + 1][kk] = __high2half(h2);
            Bl[buf][2 * np][kk]     = __low2half(l2);
            Bl[buf][2 * np + 1][kk] = __high2half(l2);
        }
    };

    loadAB(0, 0);
    __syncthreads();

    for (int t = 0; t < TILES; t++) {
        const int cur = t & 1;
        if (t + 1 < TILES) loadAB(t + 1, cur ^ 1);

        uint32_t bh[4][2], bl[4][2];
#pragma unroll
        for (int nf = 0; nf < 4; nf++) {
            int c = wn * 32 + nf * 8 + g;
            bh[nf][0] = *(const uint32_t*)&Bh[cur][c][2 * tig];
            bh[nf][1] = *(const uint32_t*)&Bh[cur][c][2 * tig + 8];
            bl[nf][0] = *(const uint32_t*)&Bl[cur][c][2 * tig];
            bl[nf][1] = *(const uint32_t*)&Bl[cur][c][2 * tig + 8];
        }
#pragma unroll
        for (int mf = 0; mf < 4; mf++) {
            int r  = wm * 64 + mf * 16 + g;
            uint32_t ah0 = *(const uint32_t*)&Ah[cur][r][2 * tig];
            uint32_t ah1 = *(const uint32_t*)&Ah[cur][r + 8][2 * tig];
            uint32_t ah2 = *(const uint32_t*)&Ah[cur][r][2 * tig + 8];
            uint32_t ah3 = *(const uint32_t*)&Ah[cur][r + 8][2 * tig + 8];
            uint32_t al0 = *(const uint32_t*)&Al[cur][r][2 * tig];
            uint32_t al1 = *(const uint32_t*)&Al[cur][r + 8][2 * tig];
            uint32_t al2 = *(const uint32_t*)&Al[cur][r][2 * tig + 8];
            uint32_t al3 = *(const uint32_t*)&Al[cur][r + 8][2 * tig + 8];
#pragma unroll
            for (int nf = 0; nf < 4; nf++) {
                mma_f16(acc[mf][nf], ah0, ah1, ah2, ah3, bh[nf][0], bh[nf][1]);
                mma_f16(acc[mf][nf], al0, al1, al2, al3, bh[nf][0], bh[nf][1]);
                mma_f16(acc[mf][nf], ah0, ah1, ah2, ah3, bl[nf][0], bl[nf][1]);
            }
        }
        __syncthreads();
    }

    // epilogue: pack adjacent-column pairs (c, c+1) to half2, single 4B store
#pragma unroll
    for (int mf = 0; mf < 4; mf++) {
        int r0 = rowBase + wm * 64 + mf * 16 + g;
        int r1 = r0 + 8;
#pragma unroll
        for (int nf = 0; nf < 4; nf++) {
            int c = wn * 32 + nf * 8 + 2 * tig;   // even
            if (r0 < n1)
                Gh2[(size_t)r0 * 64 + (c >> 1)] = pack_f2(acc[mf][nf][0], acc[mf][nf][1]);
            if (r1 < n1)
                Gh2[(size_t)r1 * 64 + (c >> 1)] = pack_f2(acc[mf][nf][2], acc[mf][nf][3]);
        }
    }
}

// ---------------- fused aggregation: warp per node in [n0,n1), CSR, no atomics --------
// Gather source g is packed half2 (4 halfs = uint2 per lane); accumulate fp32.
// EDGE_SCALE=true  (layer 1): acc = dinv[i]*g[i] + Σ dinv[s]*g[s];
//      h' = dinv[i]*relu(dinv[i]*acc + b), written SPLIT as packed half2 hi/lo
// EDGE_SCALE=false (layer 2): acc = g[i] + Σ g[s]; h = relu(dinv[i]*acc + b)
// FINAL=true: classifier out = h @ Wc + bc (warp reduce)

template <bool EDGE_SCALE, bool FINAL>
__global__ __launch_bounds__(256)
void agg_fused_kernel(const uint2* __restrict__ g, const int* __restrict__ csr,
                      const int* __restrict__ rowptr,
                      const float* __restrict__ dinv, const float4* __restrict__ bias,
                      uint2* __restrict__ hh2, uint2* __restrict__ hl2,
                      const float4* __restrict__ Wc4, const float* __restrict__ bc,
                      float2* __restrict__ out, int n0, int n1) {
    int node = n0 + ((blockIdx.x * blockDim.x + threadIdx.x) >> 5);
    int lane = threadIdx.x & 31;
    if (node >= n1) return;

    const int start = rowptr[node];
    const int end   = rowptr[node + 1];
    const int cnt   = end - start;
    const float s   = dinv[node];

    float4 a[8];
    {   // self-loop term
        float4 v = unpack_h4(g[(size_t)node * 32 + lane]);
        if (EDGE_SCALE) { v.x *= s; v.y *= s; v.z *= s; v.w *= s; }
        a[0] = v;
    }
#pragma unroll
    for (int i = 1; i < 8; i++) a[i] = make_float4(0.f, 0.f, 0.f, 0.f);

    int j = 0;
    for (; j + 8 <= cnt; j += 8) {
        int idx[8];
#pragma unroll
        for (int u = 0; u < 8; u++) idx[u] = __ldg(&csr[start + j + u]);
        uint2 raw[8];
#pragma unroll
        for (int u = 0; u < 8; u++) raw[u] = g[(size_t)idx[u] * 32 + lane];
        float dv[8];
        if (EDGE_SCALE) {
#pragma unroll
            for (int u = 0; u < 8; u++) dv[u] = __ldg(&dinv[idx[u]]);
        }
#pragma unroll
        for (int u = 0; u < 8; u++) {
            float4 v = unpack_h4(raw[u]);
            if (EDGE_SCALE) {
                a[u].x = fmaf(dv[u], v.x, a[u].x);
                a[u].y = fmaf(dv[u], v.y, a[u].y);
                a[u].z = fmaf(dv[u], v.z, a[u].z);
                a[u].w = fmaf(dv[u], v.w, a[u].w);
            } else {
                a[u].x += v.x; a[u].y += v.y; a[u].z += v.z; a[u].w += v.w;
            }
        }
    }
    if (j + 4 <= cnt) {
        int idx[4];
#pragma unroll
        for (int u = 0; u < 4; u++) idx[u] = __ldg(&csr[start + j + u]);
        uint2 raw[4];
#pragma unroll
        for (int u = 0; u < 4; u++) raw[u] = g[(size_t)idx[u] * 32 + lane];
        float dv[4];
        if (EDGE_SCALE) {
#pragma unroll
            for (int u = 0; u < 4; u++) dv[u] = __ldg(&dinv[idx[u]]);
        }
#pragma unroll
        for (int u = 0; u < 4; u++) {
            float4 v = unpack_h4(raw[u]);
            if (EDGE_SCALE) {
                a[u].x = fmaf(dv[u], v.x, a[u].x);
                a[u].y = fmaf(dv[u], v.y, a[u].y);
                a[u].z = fmaf(dv[u], v.z, a[u].z);
                a[u].w = fmaf(dv[u], v.w, a[u].w);
            } else {
                a[u].x += v.x; a[u].y += v.y; a[u].z += v.z; a[u].w += v.w;
            }
        }
        j += 4;
    }
    for (; j < cnt; j++) {
        int s0 = __ldg(&csr[start + j]);
        float4 v = unpack_h4(g[(size_t)s0 * 32 + lane]);
        if (EDGE_SCALE) {
            float d0 = __ldg(&dinv[s0]);
            a[0].x = fmaf(d0, v.x, a[0].x);
            a[0].y = fmaf(d0, v.y, a[0].y);
            a[0].z = fmaf(d0, v.z, a[0].z);
            a[0].w = fmaf(d0, v.w, a[0].w);
        } else {
            a[0].x += v.x; a[0].y += v.y; a[0].z += v.z; a[0].w += v.w;
        }
    }

    float4 acc;
    acc.x = ((a[0].x + a[1].x) + (a[2].x + a[3].x)) + ((a[4].x + a[5].x) + (a[6].x + a[7].x));
    acc.y = ((a[0].y + a[1].y) + (a[2].y + a[3].y)) + ((a[4].y + a[5].y) + (a[6].y + a[7].y));
    acc.z = ((a[0].z + a[1].z) + (a[2].z + a[3].z)) + ((a[4].z + a[5].z) + (a[6].z + a[7].z));
    acc.w = ((a[0].w + a[1].w) + (a[2].w + a[3].w)) + ((a[4].w + a[5].w) + (a[6].w + a[7].w));

    float4 bv = bias[lane];
    float4 hv;
    hv.x = fmaxf(fmaf(s, acc.x, bv.x), 0.f);
    hv.y = fmaxf(fmaf(s, acc.y, bv.y), 0.f);
    hv.z = fmaxf(fmaf(s, acc.z, bv.z), 0.f);
    hv.w = fmaxf(fmaf(s, acc.w, bv.w), 0.f);

    if (!FINAL) {
        if (EDGE_SCALE) {   // pre-scale for next layer's source role
            hv.x *= s; hv.y *= s; hv.z *= s; hv.w *= s;
        }
        // write pre-split halves (hi/lo), packed as k-pairs
        __half hx, lx, hy, ly, hz, lz, hw, lw;
        split_h(hv.x, hx, lx);
        split_h(hv.y, hy, ly);
        split_h(hv.z, hz, lz);
        split_h(hv.w, hw, lw);
        uint2 vh, vl;
        vh.x = pack_h2(hx, hy); vh.y = pack_h2(hz, hw);
        vl.x = pack_h2(lx, ly); vl.y = pack_h2(lz, lw);
        hh2[(size_t)node * 32 + lane] = vh;
        hl2[(size_t)node * 32 + lane] = vl;
    } else {
        float4 w0 = __ldg(&Wc4[lane * 2]);
        float4 w1 = __ldg(&Wc4[lane * 2 + 1]);
        float p0 = hv.x * w0.x + hv.y * w0.z + hv.z * w1.x + hv.w * w1.z;
        float p1 = hv.x * w0.y + hv.y * w0.w + hv.z * w1.y + hv.w * w1.w;
#pragma unroll
        for (int off = 16; off; off >>= 1) {
            p0 += __shfl_xor_sync(0xFFFFFFFFu, p0, off);
            p1 += __shfl_xor_sync(0xFFFFFFFFu, p1, off);
        }
        if (lane == 0) out[node] = make_float2(p0 + bc[0], p1 + bc[1]);
    }
}

// ---------------- launch ----------------

extern "C" void kernel_launch(void* const* d_in, const int* in_sizes, int n_in,
                              void* d_out, int out_size) {
    const float* x  = (const float*)d_in[0];
    const int*   ei = (const int*)d_in[1];
    const float* W1 = (const float*)d_in[2];
    const float* b1 = (const float*)d_in[3];
    const float* W2 = (const float*)d_in[4];
    const float* b2 = (const float*)d_in[5];
    const float* Wc = (const float*)d_in[6];
    const float* bc = (const float*)d_in[7];
    float* out = (float*)d_out;

    const int n = NNODES;
    const int e = in_sizes[1] / 2;
    const int* src = ei;
    const int* dst = ei + e;

    float *DINV;
    uint32_t *G, *G2, *HH2, *HL2, *W1H, *W1L, *W2H, *W2L;
    int *DEG, *ROWPTR, *CSR, *BSUMS;
    cudaGetSymbolAddress((void**)&G,      g_bufG);
    cudaGetSymbolAddress((void**)&G2,     g_bufG2);
    cudaGetSymbolAddress((void**)&HH2,    g_Hh2);
    cudaGetSymbolAddress((void**)&HL2,    g_Hl2);
    cudaGetSymbolAddress((void**)&W1H,    g_W1h2);
    cudaGetSymbolAddress((void**)&W1L,    g_W1l2);
    cudaGetSymbolAddress((void**)&W2H,    g_W2h2);
    cudaGetSymbolAddress((void**)&W2L,    g_W2l2);
    cudaGetSymbolAddress((void**)&DINV,   g_dinv);
    cudaGetSymbolAddress((void**)&DEG,    g_deg);
    cudaGetSymbolAddress((void**)&ROWPTR, g_rowptr);
    cudaGetSymbolAddress((void**)&CSR,    g_csr_src);
    cudaGetSymbolAddress((void**)&BSUMS,  g_blockSums);

    // side stream + events (host handles, created once)
    static cudaStream_t s_side = nullptr;
    static cudaEvent_t ev_fork = nullptr, ev_pre = nullptr, ev_a0 = nullptr, ev_a1 = nullptr;
    if (!s_side) {
        cudaStreamCreate(&s_side);
        cudaEventCreateWithFlags(&ev_fork, cudaEventDisableTiming);
        cudaEventCreateWithFlags(&ev_pre,  cudaEventDisableTiming);
        cudaEventCreateWithFlags(&ev_a0,   cudaEventDisableTiming);
        cudaEventCreateWithFlags(&ev_a1,   cudaEventDisableTiming);
    }

    const int c0 = CHUNK0;                       // chunk split (multiple of 128)
    const int gemmB_full = (n + 127) / 128;
    const int gemmB_c0   = c0 / 128;
    const int gemmB_c1   = (n - c0 + 127) / 128;
    const int aggB_full  = (int)(((long long)n * 32 + 255) / 256);
    const int aggB_c0    = (int)(((long long)c0 * 32 + 255) / 256);
    const int aggB_c1    = (int)(((long long)(n - c0) * 32 + 255) / 256);
    const int scanB      = (n + 2047) / 2048;

    // ---- fork: CSR build + W2 pre-split on side stream; W1 pre-split + GEMM1 on main ----
    cudaEventRecord(ev_fork, 0);
    cudaStreamWaitEvent(s_side, ev_fork, 0);

    presplit_kernel<<<(HID * 64 + 255) / 256, 256, 0, s_side>>>(W2, W2H, W2L, HID * 64);
    deg_kernel<<<(e + 255) / 256, 256, 0, s_side>>>(dst, DEG, e);
    scan_block_sums<<<scanB, 256, 0, s_side>>>(DEG, BSUMS, n);
    scan_offsets<<<1, 32, 0, s_side>>>(BSUMS, scanB);
    scan_final<<<scanB, 256, 0, s_side>>>(DEG, BSUMS, ROWPTR, DINV, n);
    scatter_kernel<<<(e + 255) / 256, 256, 0, s_side>>>(src, dst, ROWPTR, DEG, CSR, e);
    cudaEventRecord(ev_pre, s_side);

    presplit_kernel<<<(IN_F * 64 + 255) / 256, 256>>>(W1, W1H, W1L, IN_F * 64);
    gemm_kernel<IN_F, false><<<gemmB_full, 256>>>(x, nullptr, nullptr, W1H, W1L, G, 0, n);

    // ---- join preprocessing, then pipelined agg1 / GEMM2 ----
    cudaStreamWaitEvent(0, ev_pre, 0);

    // agg1 chunk 0 on main (gathers G fp16, writes Hh2/Hl2[0,c0))
    agg_fused_kernel<true, false><<<aggB_c0, 256>>>((const uint2*)G, CSR, ROWPTR, DINV,
                                                    (const float4*)b1,
                                                    (uint2*)HH2, (uint2*)HL2,
                                                    nullptr, nullptr, nullptr, 0, c0);
    cudaEventRecord(ev_a0, 0);

    // agg1 chunk 1 on side — concurrent with GEMM2 chunk 0
    cudaStreamWaitEvent(s_side, ev_a0, 0);
    agg_fused_kernel<true, false><<<aggB_c1, 256, 0, s_side>>>((const uint2*)G, CSR, ROWPTR, DINV,
                                                               (const float4*)b1,
                                                               (uint2*)HH2, (uint2*)HL2,
                                                               nullptr, nullptr, nullptr, c0, n);
    cudaEventRecord(ev_a1, s_side);

    // GEMM2 chunk 0 on main: reads Hh2/Hl2[0,c0), writes G2[0,c0) (fp16 packed)
    gemm_kernel<HID, true><<<gemmB_c0, 256>>>(nullptr, HH2, HL2, W2H, W2L, G2, 0, c0);

    // GEMM2 chunk 1 after agg1(C1) completes
    cudaStreamWaitEvent(0, ev_a1, 0);
    gemm_kernel<HID, true><<<gemmB_c1, 256>>>(nullptr, HH2, HL2, W2H, W2L, G2, c0, n);

    // ---- layer 2 aggregation + fused classifier (gathers G2 fp16) ----
    agg_fused_kernel<false, true><<<aggB_full, 256>>>((const uint2*)G2, CSR, ROWPTR, DINV,
                                                      (const float4*)b2,
                                                      nullptr, nullptr,
                                                      (const float4*)Wc, bc, (float2*)out, 0, n);
}

// round 14
// speedup vs baseline: 1.6288x; 1.2404x over previous
#include <cuda_runtime.h>
#include <cuda_fp16.h>
#include <cstdint>

#define NNODES 100000
#define EDGES  1600000
#define IN_F   165
#define HID    128
#define CHUNK0 50048   // 391 * 128

// Scratch (allocation-free rule: __device__ globals)
__device__ uint32_t g_bufG[(size_t)NNODES * 64];    // layer-1 GEMM out, packed half2 (k-pairs)
__device__ uint32_t g_bufG2[(size_t)NNODES * 64];   // layer-2 GEMM out, packed half2
__device__ uint32_t g_bufH[(size_t)NNODES * 64];    // layer-1 activation, packed half2
__device__ uint32_t g_W1h2[IN_F * 64];              // W1 fp16 (n-pairs)
__device__ uint32_t g_W2h2[HID * 64];               // W2 fp16
__device__ int      g_deg[NNODES];                  // self-restoring
__device__ float    g_dinv[NNODES];
__device__ int      g_rowptr[NNODES + 1];
__device__ int      g_csr_src[EDGES];
__device__ int      g_blockSums[128];

// ---------------- fp16 helpers ----------------

__device__ __forceinline__ uint32_t pack_f2(float a, float b) {
    __half2 t = __floats2half2_rn(a, b);
    return *(uint32_t*)&t;
}

__device__ __forceinline__ float4 unpack_h4(uint2 u) {
    float2 fa = __half22float2(*(__half2*)&u.x);
    float2 fb = __half22float2(*(__half2*)&u.y);
    return make_float4(fa.x, fa.y, fb.x, fb.y);
}

__device__ __forceinline__ void mma_f16(float* d, uint32_t a0, uint32_t a1,
                                        uint32_t a2, uint32_t a3,
                                        uint32_t b0, uint32_t b1) {
    asm volatile(
        "mma.sync.aligned.m16n8k16.row.col.f32.f16.f16.f32 "
        "{%0,%1,%2,%3}, {%4,%5,%6,%7}, {%8,%9}, {%0,%1,%2,%3};"
        : "+f"(d[0]), "+f"(d[1]), "+f"(d[2]), "+f"(d[3])
        : "r"(a0), "r"(a1), "r"(a2), "r"(a3), "r"(b0), "r"(b1));
}

// ---------------- W pre-convert: float [K][128] -> packed half2 [K][64] --------

__global__ void preconv_kernel(const float* __restrict__ W,
                               uint32_t* __restrict__ Wh2, int n2) {
    int i = blockIdx.x * blockDim.x + threadIdx.x;
    if (i < n2) Wh2[i] = pack_f2(W[2 * i], W[2 * i + 1]);
}

// ---------------- degree ----------------

__global__ void deg_kernel(const int* __restrict__ dst, int* __restrict__ deg, int e) {
    int i = blockIdx.x * blockDim.x + threadIdx.x;
    if (i < e) atomicAdd(&deg[dst[i]], 1);
}

// ---------------- exclusive prefix scan of deg -> rowptr; also dinv ----------------

__global__ __launch_bounds__(256)
void scan_block_sums(const int* __restrict__ deg, int* __restrict__ blockSums, int n) {
    __shared__ int sdata[256];
    int base = blockIdx.x * 2048;
    int tid = threadIdx.x;
    int s = 0;
#pragma unroll
    for (int j = 0; j < 8; j++) {
        int i = base + tid * 8 + j;
        if (i < n) s += deg[i];
    }
    sdata[tid] = s;
    __syncthreads();
    for (int off = 128; off; off >>= 1) {
        if (tid < off) sdata[tid] += sdata[tid + off];
        __syncthreads();
    }
    if (tid == 0) blockSums[blockIdx.x] = sdata[0];
}

__global__ void scan_offsets(int* __restrict__ blockSums, int nb) {
    int lane = threadIdx.x;            // 32 threads
    int v0 = (lane      < nb) ? blockSums[lane]      : 0;
    int v1 = (lane + 32 < nb) ? blockSums[lane + 32] : 0;
    int s0 = v0;
#pragma unroll
    for (int off = 1; off < 32; off <<= 1) {
        int t = __shfl_up_sync(0xFFFFFFFFu, s0, off);
        if (lane >= off) s0 += t;
    }
    int total0 = __shfl_sync(0xFFFFFFFFu, s0, 31);
    int s1 = v1;
#pragma unroll
    for (int off = 1; off < 32; off <<= 1) {
        int t = __shfl_up_sync(0xFFFFFFFFu, s1, off);
        if (lane >= off) s1 += t;
    }
    if (lane      < nb) blockSums[lane]      = s0 - v0;            // exclusive
    if (lane + 32 < nb) blockSums[lane + 32] = total0 + s1 - v1;
}

__global__ __launch_bounds__(256)
void scan_final(const int* __restrict__ deg, const int* __restrict__ blockSums,
                int* __restrict__ rowptr, float* __restrict__ dinv, int n) {
    __shared__ int tsum[256];
    int base = blockIdx.x * 2048;
    int tid = threadIdx.x;
    int loc[8];
    int dv[8];
    int s = 0;
#pragma unroll
    for (int j = 0; j < 8; j++) {
        int i = base + tid * 8 + j;
        int v = (i < n) ? deg[i] : 0;
        dv[j]  = v;
        loc[j] = s;
        s += v;
    }
    tsum[tid] = s;
    __syncthreads();
    for (int off = 1; off < 256; off <<= 1) {
        int t = (tid >= off) ? tsum[tid - off] : 0;
        __syncthreads();
        tsum[tid] += t;
        __syncthreads();
    }
    int threadOff = tsum[tid] - s;  // exclusive within block
    int cOff = blockSums[blockIdx.x];
#pragma unroll
    for (int j = 0; j < 8; j++) {
        int i = base + tid * 8 + j;
        if (i < n) {
            int rp = cOff + threadOff + loc[j];
            rowptr[i] = rp;
            dinv[i]   = rsqrtf((float)(dv[j] + 1));   // +1 self-loop
            if (i == n - 1) rowptr[n] = rp + dv[j];
        }
    }
}

// ---------------- scatter edges into CSR slots (counts deg back down to 0) ----------

__global__ void scatter_kernel(const int* __restrict__ src, const int* __restrict__ dst,
                               const int* __restrict__ rowptr, int* __restrict__ deg,
                               int* __restrict__ csr, int e) {
    int i = blockIdx.x * blockDim.x + threadIdx.x;
    if (i < e) {
        int d = dst[i];
        int pos = rowptr[d] + atomicAdd(&deg[d], -1) - 1;   // unique slot; deg ends at 0
        csr[pos] = src[i];
    }
}

// ---------------- GEMM (pure fp16 HMMA, fp32 accum): -------------------------------
// Gh2[r0..n1, 64] = packed-half2( A[r0..n1,K] @ W[K,128] )
// 128x128 tile, BK=16, 256 threads = 8 warps (2x4), warp tile 64x32 = 4x4 m16n8k16.
// PRE=true : A supplied as packed half2 (k-pairs)  [GEMM2: H]
// PRE=false: A is float, converted in-kernel       [GEMM1: x]

template <int K, bool PRE>
__global__ __launch_bounds__(256)
void gemm_kernel(const float* __restrict__ A,
                 const uint32_t* __restrict__ Ah2,
                 const uint32_t* __restrict__ Wh2,
                 uint32_t* __restrict__ Gh2, int row0, int n1) {
    constexpr int BM = 128, BK = 16;
    constexpr int LDK = 20;                      // half row stride (40B)
    constexpr int TILES = (K + BK - 1) / BK;

    __shared__ __align__(16) __half Ah[2][BM][LDK];
    __shared__ __align__(16) __half Bh[2][128][LDK];

    const int tid  = threadIdx.x;
    const int wid  = tid >> 5;
    const int lane = tid & 31;
    const int g    = lane >> 2;   // group 0..7
    const int tig  = lane & 3;    // thread-in-group 0..3
    const int wm   = wid & 1;     // 0..1 -> 64 rows each
    const int wn   = wid >> 1;    // 0..3 -> 32 cols each
    const int rowBase = row0 + blockIdx.x * BM;

    float acc[4][4][4];
#pragma unroll
    for (int mf = 0; mf < 4; mf++)
#pragma unroll
        for (int nf = 0; nf < 4; nf++)
#pragma unroll
            for (int q = 0; q < 4; q++) acc[mf][nf][q] = 0.f;

    auto loadAB = [&](int t, int buf) {
        const int k0 = t * BK;
        // ---- A tile: 1024 k-pairs, 4 per thread ----
        if (PRE) {
#pragma unroll
            for (int j = 0; j < 4; j++) {
                int q = tid + 256 * j;
                int r = q >> 3, kp = q & 7;
                int gr = rowBase + r;
                uint32_t vh = 0;
                if (gr < n1) vh = Ah2[(size_t)gr * 64 + (k0 >> 1) + kp];
                *(uint32_t*)&Ah[buf][r][2 * kp] = vh;
            }
        } else {
#pragma unroll
            for (int j = 0; j < 4; j++) {
                int q = tid + 256 * j;
                int r = q >> 3, kp = q & 7;
                int gr = rowBase + r;
                int gk = k0 + 2 * kp;
                float v0 = 0.f, v1 = 0.f;
                if (gr < n1) {
                    if (gk     < K) v0 = A[(size_t)gr * K + gk];
                    if (gk + 1 < K) v1 = A[(size_t)gr * K + gk + 1];
                }
                *(uint32_t*)&Ah[buf][r][2 * kp] = pack_f2(v0, v1);
            }
        }
        // ---- B tile from fp16 W: 1024 n-pairs, 4 per thread (transposed store) --
#pragma unroll
        for (int j = 0; j < 4; j++) {
            int l  = tid + 256 * j;
            int kk = l >> 6, np = l & 63;
            int gk = k0 + kk;
            uint32_t vh = 0;
            if (gk < K) vh = Wh2[gk * 64 + np];
            __half2 h2 = *(__half2*)&vh;
            Bh[buf][2 * np][kk]     = __low2half(h2);
            Bh[buf][2 * np + 1][kk] = __high2half(h2);
        }
    };

    loadAB(0, 0);
    __syncthreads();

    for (int t = 0; t < TILES; t++) {
        const int cur = t & 1;
        if (t + 1 < TILES) loadAB(t + 1, cur ^ 1);

        uint32_t bh[4][2];
#pragma unroll
        for (int nf = 0; nf < 4; nf++) {
            int c = wn * 32 + nf * 8 + g;
            bh[nf][0] = *(const uint32_t*)&Bh[cur][c][2 * tig];
            bh[nf][1] = *(const uint32_t*)&Bh[cur][c][2 * tig + 8];
        }
#pragma unroll
        for (int mf = 0; mf < 4; mf++) {
            int r  = wm * 64 + mf * 16 + g;
            uint32_t a0 = *(const uint32_t*)&Ah[cur][r][2 * tig];
            uint32_t a1 = *(const uint32_t*)&Ah[cur][r + 8][2 * tig];
            uint32_t a2 = *(const uint32_t*)&Ah[cur][r][2 * tig + 8];
            uint32_t a3 = *(const uint32_t*)&Ah[cur][r + 8][2 * tig + 8];
#pragma unroll
            for (int nf = 0; nf < 4; nf++)
                mma_f16(acc[mf][nf], a0, a1, a2, a3, bh[nf][0], bh[nf][1]);
        }
        __syncthreads();
    }

    // epilogue: pack adjacent-column pairs (c, c+1) to half2, single 4B store
#pragma unroll
    for (int mf = 0; mf < 4; mf++) {
        int r0 = rowBase + wm * 64 + mf * 16 + g;
        int r1 = r0 + 8;
#pragma unroll
        for (int nf = 0; nf < 4; nf++) {
            int c = wn * 32 + nf * 8 + 2 * tig;   // even
            if (r0 < n1)
                Gh2[(size_t)r0 * 64 + (c >> 1)] = pack_f2(acc[mf][nf][0], acc[mf][nf][1]);
            if (r1 < n1)
                Gh2[(size_t)r1 * 64 + (c >> 1)] = pack_f2(acc[mf][nf][2], acc[mf][nf][3]);
        }
    }
}

// ---------------- fused aggregation: warp per node in [n0,n1), CSR, no atomics --------
// Gather source g is packed half2 (4 halfs = uint2 per lane); accumulate fp32.
// EDGE_SCALE=true  (layer 1): acc = dinv[i]*g[i] + Σ dinv[s]*g[s];
//      h' = dinv[i]*relu(dinv[i]*acc + b), written as packed half2
// EDGE_SCALE=false (layer 2): acc = g[i] + Σ g[s]; h = relu(dinv[i]*acc + b)
// FINAL=true: classifier out = h @ Wc + bc (warp reduce)

template <bool EDGE_SCALE, bool FINAL>
__global__ __launch_bounds__(256)
void agg_fused_kernel(const uint2* __restrict__ g, const int* __restrict__ csr,
                      const int* __restrict__ rowptr,
                      const float* __restrict__ dinv, const float4* __restrict__ bias,
                      uint2* __restrict__ h,
                      const float4* __restrict__ Wc4, const float* __restrict__ bc,
                      float2* __restrict__ out, int n0, int n1) {
    int node = n0 + ((blockIdx.x * blockDim.x + threadIdx.x) >> 5);
    int lane = threadIdx.x & 31;
    if (node >= n1) return;

    const int start = rowptr[node];
    const int end   = rowptr[node + 1];
    const int cnt   = end - start;
    const float s   = dinv[node];

    float4 a[8];
    {   // self-loop term
        float4 v = unpack_h4(g[(size_t)node * 32 + lane]);
        if (EDGE_SCALE) { v.x *= s; v.y *= s; v.z *= s; v.w *= s; }
        a[0] = v;
    }
#pragma unroll
    for (int i = 1; i < 8; i++) a[i] = make_float4(0.f, 0.f, 0.f, 0.f);

    int j = 0;
    for (; j + 8 <= cnt; j += 8) {
        int idx[8];
#pragma unroll
        for (int u = 0; u < 8; u++) idx[u] = __ldg(&csr[start + j + u]);
        uint2 raw[8];
#pragma unroll
        for (int u = 0; u < 8; u++) raw[u] = g[(size_t)idx[u] * 32 + lane];
        float dv[8];
        if (EDGE_SCALE) {
#pragma unroll
            for (int u = 0; u < 8; u++) dv[u] = __ldg(&dinv[idx[u]]);
        }
#pragma unroll
        for (int u = 0; u < 8; u++) {
            float4 v = unpack_h4(raw[u]);
            if (EDGE_SCALE) {
                a[u].x = fmaf(dv[u], v.x, a[u].x);
                a[u].y = fmaf(dv[u], v.y, a[u].y);
                a[u].z = fmaf(dv[u], v.z, a[u].z);
                a[u].w = fmaf(dv[u], v.w, a[u].w);
            } else {
                a[u].x += v.x; a[u].y += v.y; a[u].z += v.z; a[u].w += v.w;
            }
        }
    }
    if (j + 4 <= cnt) {
        int idx[4];
#pragma unroll
        for (int u = 0; u < 4; u++) idx[u] = __ldg(&csr[start + j + u]);
        uint2 raw[4];
#pragma unroll
        for (int u = 0; u < 4; u++) raw[u] = g[(size_t)idx[u] * 32 + lane];
        float dv[4];
        if (EDGE_SCALE) {
#pragma unroll
            for (int u = 0; u < 4; u++) dv[u] = __ldg(&dinv[idx[u]]);
        }
#pragma unroll
        for (int u = 0; u < 4; u++) {
            float4 v = unpack_h4(raw[u]);
            if (EDGE_SCALE) {
                a[u].x = fmaf(dv[u], v.x, a[u].x);
                a[u].y = fmaf(dv[u], v.y, a[u].y);
                a[u].z = fmaf(dv[u], v.z, a[u].z);
                a[u].w = fmaf(dv[u], v.w, a[u].w);
            } else {
                a[u].x += v.x; a[u].y += v.y; a[u].z += v.z; a[u].w += v.w;
            }
        }
        j += 4;
    }
    for (; j < cnt; j++) {
        int s0 = __ldg(&csr[start + j]);
        float4 v = unpack_h4(g[(size_t)s0 * 32 + lane]);
        if (EDGE_SCALE) {
            float d0 = __ldg(&dinv[s0]);
            a[0].x = fmaf(d0, v.x, a[0].x);
            a[0].y = fmaf(d0, v.y, a[0].y);
            a[0].z = fmaf(d0, v.z, a[0].z);
            a[0].w = fmaf(d0, v.w, a[0].w);
        } else {
            a[0].x += v.x; a[0].y += v.y; a[0].z += v.z; a[0].w += v.w;
        }
    }

    float4 acc;
    acc.x = ((a[0].x + a[1].x) + (a[2].x + a[3].x)) + ((a[4].x + a[5].x) + (a[6].x + a[7].x));
    acc.y = ((a[0].y + a[1].y) + (a[2].y + a[3].y)) + ((a[4].y + a[5].y) + (a[6].y + a[7].y));
    acc.z = ((a[0].z + a[1].z) + (a[2].z + a[3].z)) + ((a[4].z + a[5].z) + (a[6].z + a[7].z));
    acc.w = ((a[0].w + a[1].w) + (a[2].w + a[3].w)) + ((a[4].w + a[5].w) + (a[6].w + a[7].w));

    float4 bv = bias[lane];
    float4 hv;
    hv.x = fmaxf(fmaf(s, acc.x, bv.x), 0.f);
    hv.y = fmaxf(fmaf(s, acc.y, bv.y), 0.f);
    hv.z = fmaxf(fmaf(s, acc.z, bv.z), 0.f);
    hv.w = fmaxf(fmaf(s, acc.w, bv.w), 0.f);

    if (!FINAL) {
        if (EDGE_SCALE) {   // pre-scale for next layer's source role
            hv.x *= s; hv.y *= s; hv.z *= s; hv.w *= s;
        }
        uint2 vh;
        vh.x = pack_f2(hv.x, hv.y);
        vh.y = pack_f2(hv.z, hv.w);
        h[(size_t)node * 32 + lane] = vh;
    } else {
        float4 w0 = __ldg(&Wc4[lane * 2]);
        float4 w1 = __ldg(&Wc4[lane * 2 + 1]);
        float p0 = hv.x * w0.x + hv.y * w0.z + hv.z * w1.x + hv.w * w1.z;
        float p1 = hv.x * w0.y + hv.y * w0.w + hv.z * w1.y + hv.w * w1.w;
#pragma unroll
        for (int off = 16; off; off >>= 1) {
            p0 += __shfl_xor_sync(0xFFFFFFFFu, p0, off);
            p1 += __shfl_xor_sync(0xFFFFFFFFu, p1, off);
        }
        if (lane == 0) out[node] = make_float2(p0 + bc[0], p1 + bc[1]);
    }
}

// ---------------- launch ----------------

extern "C" void kernel_launch(void* const* d_in, const int* in_sizes, int n_in,
                              void* d_out, int out_size) {
    const float* x  = (const float*)d_in[0];
    const int*   ei = (const int*)d_in[1];
    const float* W1 = (const float*)d_in[2];
    const float* b1 = (const float*)d_in[3];
    const float* W2 = (const float*)d_in[4];
    const float* b2 = (const float*)d_in[5];
    const float* Wc = (const float*)d_in[6];
    const float* bc = (const float*)d_in[7];
    float* out = (float*)d_out;

    const int n = NNODES;
    const int e = in_sizes[1] / 2;
    const int* src = ei;
    const int* dst = ei + e;

    float *DINV;
    uint32_t *G, *G2, *H, *W1H, *W2H;
    int *DEG, *ROWPTR, *CSR, *BSUMS;
    cudaGetSymbolAddress((void**)&G,      g_bufG);
    cudaGetSymbolAddress((void**)&G2,     g_bufG2);
    cudaGetSymbolAddress((void**)&H,      g_bufH);
    cudaGetSymbolAddress((void**)&W1H,    g_W1h2);
    cudaGetSymbolAddress((void**)&W2H,    g_W2h2);
    cudaGetSymbolAddress((void**)&DINV,   g_dinv);
    cudaGetSymbolAddress((void**)&DEG,    g_deg);
    cudaGetSymbolAddress((void**)&ROWPTR, g_rowptr);
    cudaGetSymbolAddress((void**)&CSR,    g_csr_src);
    cudaGetSymbolAddress((void**)&BSUMS,  g_blockSums);

    // side stream + events (host handles, created once)
    static cudaStream_t s_side = nullptr;
    static cudaEvent_t ev_fork = nullptr, ev_pre = nullptr, ev_a0 = nullptr, ev_a1 = nullptr;
    if (!s_side) {
        cudaStreamCreate(&s_side);
        cudaEventCreateWithFlags(&ev_fork, cudaEventDisableTiming);
        cudaEventCreateWithFlags(&ev_pre,  cudaEventDisableTiming);
        cudaEventCreateWithFlags(&ev_a0,   cudaEventDisableTiming);
        cudaEventCreateWithFlags(&ev_a1,   cudaEventDisableTiming);
    }

    const int c0 = CHUNK0;                       // chunk split (multiple of 128)
    const int gemmB_full = (n + 127) / 128;
    const int gemmB_c0   = c0 / 128;
    const int gemmB_c1   = (n - c0 + 127) / 128;
    const int aggB_full  = (int)(((long long)n * 32 + 255) / 256);
    const int aggB_c0    = (int)(((long long)c0 * 32 + 255) / 256);
    const int aggB_c1    = (int)(((long long)(n - c0) * 32 + 255) / 256);
    const int scanB      = (n + 2047) / 2048;

    // ---- fork: CSR build + W2 convert on side stream; W1 convert + GEMM1 on main ----
    cudaEventRecord(ev_fork, 0);
    cudaStreamWaitEvent(s_side, ev_fork, 0);

    preconv_kernel<<<(HID * 64 + 255) / 256, 256, 0, s_side>>>(W2, W2H, HID * 64);
    deg_kernel<<<(e + 255) / 256, 256, 0, s_side>>>(dst, DEG, e);
    scan_block_sums<<<scanB, 256, 0, s_side>>>(DEG, BSUMS, n);
    scan_offsets<<<1, 32, 0, s_side>>>(BSUMS, scanB);
    scan_final<<<scanB, 256, 0, s_side>>>(DEG, BSUMS, ROWPTR, DINV, n);
    scatter_kernel<<<(e + 255) / 256, 256, 0, s_side>>>(src, dst, ROWPTR, DEG, CSR, e);
    cudaEventRecord(ev_pre, s_side);

    preconv_kernel<<<(IN_F * 64 + 255) / 256, 256>>>(W1, W1H, IN_F * 64);
    gemm_kernel<IN_F, false><<<gemmB_full, 256>>>(x, nullptr, W1H, G, 0, n);

    // ---- join preprocessing, then pipelined agg1 / GEMM2 ----
    cudaStreamWaitEvent(0, ev_pre, 0);

    // agg1 chunk 0 on main (gathers G fp16, writes H[0,c0))
    agg_fused_kernel<true, false><<<aggB_c0, 256>>>((const uint2*)G, CSR, ROWPTR, DINV,
                                                    (const float4*)b1, (uint2*)H,
                                                    nullptr, nullptr, nullptr, 0, c0);
    cudaEventRecord(ev_a0, 0);

    // agg1 chunk 1 on side — concurrent with GEMM2 chunk 0
    cudaStreamWaitEvent(s_side, ev_a0, 0);
    agg_fused_kernel<true, false><<<aggB_c1, 256, 0, s_side>>>((const uint2*)G, CSR, ROWPTR, DINV,
                                                               (const float4*)b1, (uint2*)H,
                                                               nullptr, nullptr, nullptr, c0, n);
    cudaEventRecord(ev_a1, s_side);

    // GEMM2 chunk 0 on main: reads H[0,c0), writes G2[0,c0) (fp16 packed)
    gemm_kernel<HID, true><<<gemmB_c0, 256>>>(nullptr, H, W2H, G2, 0, c0);

    // GEMM2 chunk 1 after agg1(C1) completes
    cudaStreamWaitEvent(0, ev_a1, 0);
    gemm_kernel<HID, true><<<gemmB_c1, 256>>>(nullptr, H, W2H, G2, c0, n);

    // ---- layer 2 aggregation + fused classifier (gathers G2 fp16) ----
    agg_fused_kernel<false, true><<<aggB_full, 256>>>((const uint2*)G2, CSR, ROWPTR, DINV,
                                                      (const float4*)b2, nullptr,
                                                      (const float4*)Wc, bc, (float2*)out, 0, n);
}